// round 2
// baseline (speedup 1.0000x reference)
#include <cuda_runtime.h>
#include <math.h>

#define Bz 8
#define Tz 512
#define Dz 128
#define Hz 128
#define BT (Bz*Tz)          // 4096
#define BTH (BT*Hz)         // 524288
#define Lz 2

// ---- scratch (device globals; no allocation allowed) ----
__device__ __align__(128) float gq[BTH];
__device__ __align__(128) float gk[BTH];   // pre-scaled by 1/sqrt(H)
__device__ __align__(128) float gv[BTH];
__device__ __align__(128) float gi[BTH];   // exp(zi)
__device__ __align__(128) float gf[BTH];   // sigmoid(zf)
__device__ __align__(128) float go[BTH];   // sigmoid(zo)
__device__ __align__(128) float gnprev[BTH];
__device__ __align__(128) float gden[BT];
__device__ __align__(128) float gh1[BTH];  // layer-1 output

struct GemmArgs {
  const float* X;          // layer input (ignored if use_h1)
  const float* W[6];       // per-projection weights (H x D row-major), layer offset applied
  const float* bias[6];    // per-projection bias (H), layer offset applied
  int use_h1;
};

// ---------------------------------------------------------------------------
// Kernel 1: fused 6-way projection GEMM + activations.
// out[n, m] = act_p( sum_d X[n,d] * W_p[m,d] + b_p[m] )
// grid (BT/64, 12): blockIdx.y -> projection p = y>>1, half mbase = (y&1)*64
// ---------------------------------------------------------------------------
__global__ __launch_bounds__(256) void gemm_act(GemmArgs a) {
  __shared__ float As[64 * 65];   // [n][k], stride 65 (conflict-free)
  __shared__ float Bs[64 * 65];   // [m][k]
  const float* Xp = a.use_h1 ? gh1 : a.X;

  int tid = threadIdx.x;
  int n0 = blockIdx.x * 64;
  int by = blockIdx.y;
  int p = by >> 1;
  int mbase = (by & 1) * 64;
  const float* Wp = a.W[p];

  int tx = tid & 15, ty = tid >> 4;

  float acc[4][4];
#pragma unroll
  for (int i = 0; i < 4; i++)
#pragma unroll
    for (int j = 0; j < 4; j++) acc[i][j] = 0.f;

  for (int kk = 0; kk < Dz; kk += 64) {
#pragma unroll
    for (int s = 0; s < 16; s++) {
      int idx = (s << 8) | tid;       // 0..4095
      int r = idx >> 6, kl = idx & 63;
      As[r * 65 + kl] = Xp[(n0 + r) * Dz + kk + kl];
      Bs[r * 65 + kl] = Wp[(mbase + r) * Dz + kk + kl];
    }
    __syncthreads();
#pragma unroll 8
    for (int k = 0; k < 64; k++) {
      float av[4], bv[4];
#pragma unroll
      for (int i = 0; i < 4; i++) av[i] = As[(ty * 4 + i) * 65 + k];
#pragma unroll
      for (int j = 0; j < 4; j++) bv[j] = Bs[(tx * 4 + j) * 65 + k];
#pragma unroll
      for (int i = 0; i < 4; i++)
#pragma unroll
        for (int j = 0; j < 4; j++)
          acc[i][j] = fmaf(av[i], bv[j], acc[i][j]);
    }
    __syncthreads();
  }

  float* outs;
  switch (p) {
    case 0: outs = gq; break;
    case 1: outs = gk; break;
    case 2: outs = gv; break;
    case 3: outs = gi; break;
    case 4: outs = gf; break;
    default: outs = go; break;
  }
  const float kscale = 0.08838834764831845f;  // 1/sqrt(128)
  const float* bp = a.bias[p];
#pragma unroll
  for (int i = 0; i < 4; i++) {
    int n = n0 + ty * 4 + i;
#pragma unroll
    for (int j = 0; j < 4; j++) {
      int m = mbase + tx * 4 + j;
      float val = acc[i][j] + bp[m];
      float r;
      if (p == 0)      r = val;
      else if (p == 1) r = val * kscale;
      else if (p == 2) r = val;
      else if (p == 3) r = __expf(val);
      else             r = __fdividef(1.f, 1.f + __expf(-val));
      outs[n * Hz + m] = r;
    }
  }
}

// ---------------------------------------------------------------------------
// Kernel 2: elementwise n-scan per (b,h) channel, storing PRE-update n at t.
// n_t = f_t * n_{t-1} + i_t * k_t   (k already scaled)
// ---------------------------------------------------------------------------
__global__ void nscan_k() {
  int g = blockIdx.x * 128 + threadIdx.x;   // 0..1023
  int b = g >> 7, h = g & 127;
  float n = 0.f;
  int base = b * Tz * Hz + h;
#pragma unroll 4
  for (int t = 0; t < Tz; t++) {
    int idx = base + t * Hz;
    gnprev[idx] = n;
    n = fmaf(gf[idx], n, gi[idx] * gk[idx]);
  }
}

// ---------------------------------------------------------------------------
// Kernel 3: denom_t = max(|n_{t-1} . q_t|, 1), one warp per (b,t).
// ---------------------------------------------------------------------------
__global__ __launch_bounds__(256) void denom_k() {
  int gt = blockIdx.x * blockDim.x + threadIdx.x;
  int w = gt >> 5;            // row = b*T + t, 0..4095
  int lane = gt & 31;
  const float4* np = (const float4*)(gnprev + w * Hz);
  const float4* qp = (const float4*)(gq + w * Hz);
  float4 av = np[lane];
  float4 qv = qp[lane];
  float s = av.x * qv.x + av.y * qv.y + av.z * qv.z + av.w * qv.w;
#pragma unroll
  for (int o = 16; o; o >>= 1) s += __shfl_xor_sync(0xffffffffu, s, o);
  if (lane == 0) gden[w] = fmaxf(fabsf(s), 1.f);
}

// ---------------------------------------------------------------------------
// Kernel 4: main scan. 1 warp per block, 8 C-rows per warp, 4 lanes per row.
// lane = c*8 + r ; row i = wg*8 + r ; lane owns C[i][c*32 .. c*32+31].
// Per step: h_tilde = C_old . q_t (reduce over c via shfl-xor 8,16),
//           h = o * h_tilde / denom, then C = f*C + (i*v)*k.
// ---------------------------------------------------------------------------
__global__ __launch_bounds__(32) void scan_k(float* dout, int last) {
  int blk = blockIdx.x;       // 0..127
  int b = blk >> 4;
  int wg = blk & 15;
  int lane = threadIdx.x;
  int c = lane >> 3, r = lane & 7;
  int i = wg * 8 + r;
  float* outp = last ? dout : gh1;

  float C[32];
#pragma unroll
  for (int j = 0; j < 32; j++) C[j] = 0.f;

  int rowbase = b * Tz * Hz;
#pragma unroll 4
  for (int t = 0; t < Tz; t++) {
    int row = rowbase + t * Hz;
    const float4* q4 = (const float4*)(gq + row + c * 32);
    const float4* k4 = (const float4*)(gk + row + c * 32);
    float vv = gv[row + i];
    float it = gi[row + i];
    float ft = gf[row + i];
    float ot = go[row + i];
    float dn = gden[b * Tz + t];
    float w = it * vv;
    float a0 = 0.f, a1 = 0.f;
#pragma unroll
    for (int m = 0; m < 8; m++) {
      float4 qv = q4[m];
      float4 kv = k4[m];
      // dot with OLD C, then update C (sequenced per element)
      a0 = fmaf(C[4 * m + 0], qv.x, a0);
      C[4 * m + 0] = fmaf(ft, C[4 * m + 0], w * kv.x);
      a1 = fmaf(C[4 * m + 1], qv.y, a1);
      C[4 * m + 1] = fmaf(ft, C[4 * m + 1], w * kv.y);
      a0 = fmaf(C[4 * m + 2], qv.z, a0);
      C[4 * m + 2] = fmaf(ft, C[4 * m + 2], w * kv.z);
      a1 = fmaf(C[4 * m + 3], qv.w, a1);
      C[4 * m + 3] = fmaf(ft, C[4 * m + 3], w * kv.w);
    }
    float acc = a0 + a1;
    acc += __shfl_xor_sync(0xffffffffu, acc, 8);
    acc += __shfl_xor_sync(0xffffffffu, acc, 16);
    if (c == 0) {
      outp[row + i] = ot * __fdividef(acc, dn);
    }
  }
}

// ---------------------------------------------------------------------------
// Host launch. Graph-capturable: kernel launches only, no sync, no alloc.
// Input order resolved at runtime via in_sizes (dict order vs signature order).
// ---------------------------------------------------------------------------
extern "C" void kernel_launch(void* const* d_in, const int* in_sizes, int n_in,
                              void* d_out, int out_size) {
  const float* x = (const float*)d_in[0];
  const float* W[6];
  const float* Bb[6];

  // signature order: x, Wq, bq, Wk, bk, ... -> in_sizes[2] == L*H == 256
  // dict order:      x, Wq..Wo, bq..bo     -> in_sizes[2] == L*H*D == 32768
  if (n_in >= 13 && in_sizes[2] == Lz * Hz) {
    for (int j = 0; j < 6; j++) {
      W[j]  = (const float*)d_in[1 + 2 * j];
      Bb[j] = (const float*)d_in[2 + 2 * j];
    }
  } else {
    for (int j = 0; j < 6; j++) {
      W[j]  = (const float*)d_in[1 + j];
      Bb[j] = (const float*)d_in[7 + j];
    }
  }

  for (int l = 0; l < Lz; l++) {
    GemmArgs a;
    a.X = x;
    a.use_h1 = l;  // layer 1 reads gh1
    for (int j = 0; j < 6; j++) {
      a.W[j]    = W[j]  + l * Hz * Dz;
      a.bias[j] = Bb[j] + l * Hz;
    }
    gemm_act<<<dim3(BT / 64, 12), 256>>>(a);
    nscan_k<<<8, 128>>>();
    denom_k<<<(BT * 32) / 256, 256>>>();
    scan_k<<<128, 32>>>((float*)d_out, (l == Lz - 1) ? 1 : 0);
  }
}

// round 5
// speedup vs baseline: 1.5246x; 1.5246x over previous
#include <cuda_runtime.h>
#include <math.h>

#define Bz 8
#define Tz 512
#define Dz 128
#define Hz 128
#define BT (Bz*Tz)          // 4096
#define BTH (BT*Hz)         // 524288
#define Lz 2

// ---- scratch (device globals; no allocation allowed) ----
__device__ __align__(128) float gq[BTH];
__device__ __align__(128) float gk[BTH];   // pre-scaled by 1/sqrt(H)
__device__ __align__(128) float gv[BTH];
__device__ __align__(128) float gi[BTH];   // exp(zi)
__device__ __align__(128) float gf[BTH];   // sigmoid(zf)
__device__ __align__(128) float go[BTH];   // sigmoid(zo)
__device__ __align__(128) float gnprev[BTH];
__device__ __align__(128) float gden[BT];
__device__ __align__(128) float gh1[BTH];  // layer-1 output

struct GemmArgs {
  const float* X;
  const float* W[6];
  const float* bias[6];
  int use_h1;
};

// ---------------------------------------------------------------------------
// Kernel 1: fused 6-way projection GEMM + activations.
// ---------------------------------------------------------------------------
__global__ __launch_bounds__(256) void gemm_act(GemmArgs a) {
  __shared__ float As[64 * 65];
  __shared__ float Bs[64 * 65];
  const float* Xp = a.use_h1 ? gh1 : a.X;

  int tid = threadIdx.x;
  int n0 = blockIdx.x * 64;
  int by = blockIdx.y;
  int p = by >> 1;
  int mbase = (by & 1) * 64;
  const float* Wp = a.W[p];

  int tx = tid & 15, ty = tid >> 4;

  float acc[4][4];
#pragma unroll
  for (int i = 0; i < 4; i++)
#pragma unroll
    for (int j = 0; j < 4; j++) acc[i][j] = 0.f;

  for (int kk = 0; kk < Dz; kk += 64) {
#pragma unroll
    for (int s = 0; s < 16; s++) {
      int idx = (s << 8) | tid;
      int r = idx >> 6, kl = idx & 63;
      As[r * 65 + kl] = Xp[(n0 + r) * Dz + kk + kl];
      Bs[r * 65 + kl] = Wp[(mbase + r) * Dz + kk + kl];
    }
    __syncthreads();
#pragma unroll 8
    for (int k = 0; k < 64; k++) {
      float av[4], bv[4];
#pragma unroll
      for (int i = 0; i < 4; i++) av[i] = As[(ty * 4 + i) * 65 + k];
#pragma unroll
      for (int j = 0; j < 4; j++) bv[j] = Bs[(tx * 4 + j) * 65 + k];
#pragma unroll
      for (int i = 0; i < 4; i++)
#pragma unroll
        for (int j = 0; j < 4; j++)
          acc[i][j] = fmaf(av[i], bv[j], acc[i][j]);
    }
    __syncthreads();
  }

  float* outs;
  switch (p) {
    case 0: outs = gq; break;
    case 1: outs = gk; break;
    case 2: outs = gv; break;
    case 3: outs = gi; break;
    case 4: outs = gf; break;
    default: outs = go; break;
  }
  const float kscale = 0.08838834764831845f;  // 1/sqrt(128)
  const float* bp = a.bias[p];
#pragma unroll
  for (int i = 0; i < 4; i++) {
    int n = n0 + ty * 4 + i;
#pragma unroll
    for (int j = 0; j < 4; j++) {
      int m = mbase + tx * 4 + j;
      float val = acc[i][j] + bp[m];
      float r;
      if (p == 0)      r = val;
      else if (p == 1) r = val * kscale;
      else if (p == 2) r = val;
      else if (p == 3) r = __expf(val);
      else             r = __fdividef(1.f, 1.f + __expf(-val));
      outs[n * Hz + m] = r;
    }
  }
}

// ---------------------------------------------------------------------------
// Kernel 2: elementwise n-scan per (b,h) channel, storing PRE-update n at t.
// ---------------------------------------------------------------------------
__global__ void nscan_k() {
  int g = blockIdx.x * 128 + threadIdx.x;   // 0..1023
  int b = g >> 7, h = g & 127;
  float n = 0.f;
  int base = b * Tz * Hz + h;
#pragma unroll 4
  for (int t = 0; t < Tz; t++) {
    int idx = base + t * Hz;
    gnprev[idx] = n;
    n = fmaf(gf[idx], n, gi[idx] * gk[idx]);
  }
}

// ---------------------------------------------------------------------------
// Kernel 3: denom_t = max(|n_{t-1} . q_t|, 1), one warp per (b,t).
// ---------------------------------------------------------------------------
__global__ __launch_bounds__(256) void denom_k() {
  int gt = blockIdx.x * blockDim.x + threadIdx.x;
  int w = gt >> 5;
  int lane = gt & 31;
  const float4* np = (const float4*)(gnprev + w * Hz);
  const float4* qp = (const float4*)(gq + w * Hz);
  float4 av = np[lane];
  float4 qv = qp[lane];
  float s = av.x * qv.x + av.y * qv.y + av.z * qv.z + av.w * qv.w;
#pragma unroll
  for (int o = 16; o; o >>= 1) s += __shfl_xor_sync(0xffffffffu, s, o);
  if (lane == 0) gden[w] = fmaxf(fabsf(s), 1.f);
}

// ---------------------------------------------------------------------------
// Kernel 4: main scan, v2. ONE WARP PER C-ROW (1024 warps total).
// Row g = b*128 + i. Lane owns C[i][4*lane .. 4*lane+3].
// Per step: acc = C_old . q (4 FMA + full-warp reduce), then
//           C = f*C + (i*v)*k ; lane 0 writes h = o * acc / denom.
// 64-thread blocks (2 warps) -> grid 512 -> ~3.5 blocks/SM for balance.
// ---------------------------------------------------------------------------
__global__ __launch_bounds__(64) void scan_k(float* dout, int last) {
  int warp = threadIdx.x >> 5;
  int lane = threadIdx.x & 31;
  int g = blockIdx.x * 2 + warp;      // 0..1023
  int b = g >> 7;
  int i = g & 127;
  float* outp = last ? dout : gh1;

  float C0 = 0.f, C1 = 0.f, C2 = 0.f, C3 = 0.f;
  int rowbase = b * Tz * Hz;
  const float* denb = gden + b * Tz;
  int joff = lane * 4;

#pragma unroll 4
  for (int t = 0; t < Tz; t++) {
    int row = rowbase + t * Hz;
    float4 qv = *(const float4*)(gq + row + joff);
    float4 kv = *(const float4*)(gk + row + joff);
    float vv = gv[row + i];
    float it = gi[row + i];
    float ft = gf[row + i];
    float ot = go[row + i];
    float dn = denb[t];
    float w = it * vv;

    // dot with OLD C
    float acc = C0 * qv.x;
    acc = fmaf(C1, qv.y, acc);
    acc = fmaf(C2, qv.z, acc);
    acc = fmaf(C3, qv.w, acc);

    // update C
    C0 = fmaf(ft, C0, w * kv.x);
    C1 = fmaf(ft, C1, w * kv.y);
    C2 = fmaf(ft, C2, w * kv.z);
    C3 = fmaf(ft, C3, w * kv.w);

#pragma unroll
    for (int o = 16; o; o >>= 1) acc += __shfl_xor_sync(0xffffffffu, acc, o);
    if (lane == 0) outp[row + i] = ot * __fdividef(acc, dn);
  }
}

// ---------------------------------------------------------------------------
// Host launch.
// ---------------------------------------------------------------------------
extern "C" void kernel_launch(void* const* d_in, const int* in_sizes, int n_in,
                              void* d_out, int out_size) {
  const float* x = (const float*)d_in[0];
  const float* W[6];
  const float* Bb[6];

  if (n_in >= 13 && in_sizes[2] == Lz * Hz) {
    for (int j = 0; j < 6; j++) {
      W[j]  = (const float*)d_in[1 + 2 * j];
      Bb[j] = (const float*)d_in[2 + 2 * j];
    }
  } else {
    for (int j = 0; j < 6; j++) {
      W[j]  = (const float*)d_in[1 + j];
      Bb[j] = (const float*)d_in[7 + j];
    }
  }

  for (int l = 0; l < Lz; l++) {
    GemmArgs a;
    a.X = x;
    a.use_h1 = l;
    for (int j = 0; j < 6; j++) {
      a.W[j]    = W[j]  + l * Hz * Dz;
      a.bias[j] = Bb[j] + l * Hz;
    }
    gemm_act<<<dim3(BT / 64, 12), 256>>>(a);
    nscan_k<<<8, 128>>>();
    denom_k<<<(BT * 32) / 256, 256>>>();
    scan_k<<<512, 64>>>((float*)d_out, (l == Lz - 1) ? 1 : 0);
  }
}

// round 6
// speedup vs baseline: 1.8165x; 1.1914x over previous
#include <cuda_runtime.h>
#include <math.h>

#define Bz 8
#define Tz 512
#define Dz 128
#define Hz 128
#define BT (Bz*Tz)          // 4096
#define BTH (BT*Hz)         // 524288
#define Lz 2
#define Sc 16               // chunk size
#define NC (Tz/Sc)          // 32 chunks

// ---- scratch (device globals; no allocation allowed) ----
__device__ __align__(128) float gq[BTH];
__device__ __align__(128) float gk[BTH];     // pre-scaled by 1/sqrt(H)
__device__ __align__(128) float gv[BTH];
__device__ __align__(128) float gi[BTH];     // exp(zi)
__device__ __align__(128) float gf[BTH];     // sigmoid(zf)
__device__ __align__(128) float go[BTH];     // sigmoid(zo)
__device__ __align__(128) float gnprev[BTH];
__device__ __align__(128) float gden[BT];
__device__ __align__(128) float gh1[BTH];    // layer-1 output
// chunked-scan scratch
__device__ __align__(128) float gA[BTH];       // Ahat[s][i] = i*v / Pn[s]
__device__ __align__(128) float gPprev[BTH];   // Pn[t-1] (t=0 slot = 1/sqrt(Ptot))
__device__ __align__(128) float gsqP[Bz*NC*Hz];  // sqrt(Ptot) per (b,c,i)
__device__ __align__(128) float gPtot[Bz*NC*Hz]; // Ptot per (b,c,i)
__device__ __align__(128) float gCst[Bz*NC*Hz*Hz]; // chunk-start states (16MB)

struct GemmArgs {
  const float* X;
  const float* W[6];
  const float* bias[6];
  int use_h1;
};

// ---------------------------------------------------------------------------
// Kernel 1: fused 6-way projection GEMM + activations.
// ---------------------------------------------------------------------------
__global__ __launch_bounds__(256) void gemm_act(GemmArgs a) {
  __shared__ float As[64 * 65];
  __shared__ float Bs[64 * 65];
  const float* Xp = a.use_h1 ? gh1 : a.X;

  int tid = threadIdx.x;
  int n0 = blockIdx.x * 64;
  int by = blockIdx.y;
  int p = by >> 1;
  int mbase = (by & 1) * 64;
  const float* Wp = a.W[p];

  int tx = tid & 15, ty = tid >> 4;

  float acc[4][4];
#pragma unroll
  for (int i = 0; i < 4; i++)
#pragma unroll
    for (int j = 0; j < 4; j++) acc[i][j] = 0.f;

  for (int kk = 0; kk < Dz; kk += 64) {
#pragma unroll
    for (int s = 0; s < 16; s++) {
      int idx = (s << 8) | tid;
      int r = idx >> 6, kl = idx & 63;
      As[r * 65 + kl] = Xp[(n0 + r) * Dz + kk + kl];
      Bs[r * 65 + kl] = Wp[(mbase + r) * Dz + kk + kl];
    }
    __syncthreads();
#pragma unroll 8
    for (int k = 0; k < 64; k++) {
      float av[4], bv[4];
#pragma unroll
      for (int i = 0; i < 4; i++) av[i] = As[(ty * 4 + i) * 65 + k];
#pragma unroll
      for (int j = 0; j < 4; j++) bv[j] = Bs[(tx * 4 + j) * 65 + k];
#pragma unroll
      for (int i = 0; i < 4; i++)
#pragma unroll
        for (int j = 0; j < 4; j++)
          acc[i][j] = fmaf(av[i], bv[j], acc[i][j]);
    }
    __syncthreads();
  }

  float* outs;
  switch (p) {
    case 0: outs = gq; break;
    case 1: outs = gk; break;
    case 2: outs = gv; break;
    case 3: outs = gi; break;
    case 4: outs = gf; break;
    default: outs = go; break;
  }
  const float kscale = 0.08838834764831845f;  // 1/sqrt(128)
  const float* bp = a.bias[p];
#pragma unroll
  for (int i = 0; i < 4; i++) {
    int n = n0 + ty * 4 + i;
#pragma unroll
    for (int j = 0; j < 4; j++) {
      int m = mbase + tx * 4 + j;
      float val = acc[i][j] + bp[m];
      float r;
      if (p == 0)      r = val;
      else if (p == 1) r = val * kscale;
      else if (p == 2) r = val;
      else if (p == 3) r = __expf(val);
      else             r = __fdividef(1.f, 1.f + __expf(-val));
      outs[n * Hz + m] = r;
    }
  }
}

// ---------------------------------------------------------------------------
// Kernel 2: per-chunk log-decay cumsum -> Pn / Ahat / sqrt(Ptot) / Ptot.
// Center-shifted: Pn[t] = exp(cum[t] - cum[S-1]/2); ratios are exact.
// grid = (Bz*NC), block = 128 (one i per thread).
// ---------------------------------------------------------------------------
__global__ __launch_bounds__(128) void cum_k() {
  int bc = blockIdx.x;
  int i = threadIdx.x;
  int base = bc * Sc * Hz + i;

  float lf[Sc];
  float ct = 0.f;
#pragma unroll
  for (int t = 0; t < Sc; t++) {
    float f = gf[base + t * Hz];
    float l = __logf(f);
    lf[t] = l;
    ct += l;
  }
  float sq2 = 0.5f * ct;

  gPprev[base] = __expf(-sq2);   // t=0 slot: Pn[-1] = 1/sqrt(Ptot)
  float c_run = 0.f;
#pragma unroll
  for (int t = 0; t < Sc; t++) {
    c_run += lf[t];
    float iv = gi[base + t * Hz] * gv[base + t * Hz];
    gA[base + t * Hz] = iv * __expf(sq2 - c_run);
    if (t < Sc - 1) gPprev[base + (t + 1) * Hz] = __expf(c_run - sq2);
  }
  gsqP[bc * Hz + i]  = __expf(sq2);
  gPtot[bc * Hz + i] = __expf(ct);
}

// ---------------------------------------------------------------------------
// Kernel 3: elementwise n-scan (exact recurrence), unroll-8 batched loads.
// ---------------------------------------------------------------------------
__global__ __launch_bounds__(32) void nscan_k() {
  int g = blockIdx.x * 32 + threadIdx.x;   // 0..1023
  int b = g >> 7, h = g & 127;
  float n = 0.f;
  int base = b * Tz * Hz + h;
  for (int t0 = 0; t0 < Tz; t0 += 8) {
    float fv[8], ik[8];
#pragma unroll
    for (int u = 0; u < 8; u++) {
      int idx = base + (t0 + u) * Hz;
      fv[u] = gf[idx];
      ik[u] = gi[idx] * gk[idx];
    }
#pragma unroll
    for (int u = 0; u < 8; u++) {
      int idx = base + (t0 + u) * Hz;
      gnprev[idx] = n;
      n = fmaf(fv[u], n, ik[u]);
    }
  }
}

// ---------------------------------------------------------------------------
// Kernel 4: denom_t = max(|n_{t-1} . q_t|, 1), one warp per (b,t).
// ---------------------------------------------------------------------------
__global__ __launch_bounds__(256) void denom_k() {
  int gt = blockIdx.x * blockDim.x + threadIdx.x;
  int w = gt >> 5;
  int lane = gt & 31;
  const float4* np = (const float4*)(gnprev + w * Hz);
  const float4* qp = (const float4*)(gq + w * Hz);
  float4 av = np[lane];
  float4 qv = qp[lane];
  float s = av.x * qv.x + av.y * qv.y + av.z * qv.z + av.w * qv.w;
#pragma unroll
  for (int o = 16; o; o >>= 1) s += __shfl_xor_sync(0xffffffffu, s, o);
  if (lane == 0) gden[w] = fmaxf(fabsf(s), 1.f);
}

// ---------------------------------------------------------------------------
// Kernel 5: serial chunk-state scan (only serial part; 32 steps).
// grid = Bz, block = 1024. Thread owns C[i][jq..jq+15], i=tid>>3, jq=(tid&7)*16.
// Cend = Ptot_i * Cstart + sqrt(Ptot)_i * sum_s Ahat[s][i]*k_s[j].
// Stores Cstart of every chunk to gCst.
// ---------------------------------------------------------------------------
__global__ __launch_bounds__(1024) void state_k() {
  int b = blockIdx.x;
  int tid = threadIdx.x;
  int i = tid >> 3;
  int jq = (tid & 7) * 16;

  float C[16];
#pragma unroll
  for (int m = 0; m < 16; m++) C[m] = 0.f;

  for (int c = 0; c < NC; c++) {
    // store chunk-start state
    float4* dst = (float4*)(gCst + (((b * NC + c) * Hz + i) * Hz + jq));
#pragma unroll
    for (int m = 0; m < 4; m++)
      dst[m] = make_float4(C[4*m], C[4*m+1], C[4*m+2], C[4*m+3]);

    int rb = (b * Tz + c * Sc) * Hz;
    float sum[16];
#pragma unroll
    for (int m = 0; m < 16; m++) sum[m] = 0.f;
#pragma unroll
    for (int s = 0; s < Sc; s++) {
      float a = gA[rb + s * Hz + i];
      const float4* kr = (const float4*)(gk + rb + s * Hz + jq);
#pragma unroll
      for (int m = 0; m < 4; m++) {
        float4 kv = kr[m];
        sum[4*m]   = fmaf(a, kv.x, sum[4*m]);
        sum[4*m+1] = fmaf(a, kv.y, sum[4*m+1]);
        sum[4*m+2] = fmaf(a, kv.z, sum[4*m+2]);
        sum[4*m+3] = fmaf(a, kv.w, sum[4*m+3]);
      }
    }
    float pt = gPtot[(b * NC + c) * Hz + i];
    float sp = gsqP[(b * NC + c) * Hz + i];
#pragma unroll
    for (int m = 0; m < 16; m++) C[m] = fmaf(pt, C[m], sp * sum[m]);
  }
}

// ---------------------------------------------------------------------------
// Kernel 6: per-chunk outputs (fully parallel over (b,c)).
// h~[t][i] = Pprev[t][i] * ( sum_{s<t} G[t][s]*Ahat[s][i]
//                            + sqrt(Ptot)_i * (Cstart[i,:].q_t) )
// h = o * h~ / den.  grid = Bz*NC, block = 128 (thread = i).
// ---------------------------------------------------------------------------
__global__ __launch_bounds__(128) void out_k(float* dout, int last) {
  __shared__ float qsm[Sc][132];
  __shared__ float ksm[Sc][132];
  __shared__ float Asm[Sc][128];
  __shared__ float Gs[Sc][Sc];

  int bc = blockIdx.x;
  int b = bc >> 5;        // /NC
  int c = bc & 31;
  int tid = threadIdx.x;
  int row0 = bc * Sc * Hz;
  float* outp = last ? dout : gh1;

  // stage chunk q, k, Ahat
  for (int idx = tid; idx < Sc * Hz; idx += 128) {
    int t = idx >> 7, d = idx & 127;
    qsm[t][d] = gq[row0 + idx];
    ksm[t][d] = gk[row0 + idx];
    Asm[t][d] = gA[row0 + idx];
  }
  __syncthreads();

  // G[t][s] = k_s . q_t  (strict lower: s < t)
#pragma unroll
  for (int e0 = 0; e0 < 2; e0++) {
    int e = tid + e0 * 128;
    int t = e >> 4, s = e & 15;
    float gacc = 0.f;
    if (s < t) {
#pragma unroll 16
      for (int d = 0; d < Hz; d++) gacc = fmaf(ksm[s][d], qsm[t][d], gacc);
    }
    Gs[t][s] = gacc;
  }
  __syncthreads();

  int i = tid;
  float acc[Sc];
#pragma unroll
  for (int t = 0; t < Sc; t++) acc[t] = 0.f;

  // inter: CQ[t] = Cstart[i,:] . q_t
  const float4* crow = (const float4*)(gCst + (((long)bc * Hz + i) * Hz));
#pragma unroll 4
  for (int j4 = 0; j4 < 32; j4++) {
    float4 cv = crow[j4];
    int j = j4 * 4;
#pragma unroll
    for (int t = 0; t < Sc; t++) {
      acc[t] = fmaf(cv.x, qsm[t][j],     acc[t]);
      acc[t] = fmaf(cv.y, qsm[t][j + 1], acc[t]);
      acc[t] = fmaf(cv.z, qsm[t][j + 2], acc[t]);
      acc[t] = fmaf(cv.w, qsm[t][j + 3], acc[t]);
    }
  }
  float sp = gsqP[bc * Hz + i];
#pragma unroll
  for (int t = 0; t < Sc; t++) acc[t] *= sp;

  // intra: sum_{s<t} G[t][s] * Ahat[s][i]
#pragma unroll
  for (int s = 0; s < Sc - 1; s++) {
    float a = Asm[s][i];
#pragma unroll
    for (int t = 0; t < Sc; t++) {
      if (t > s) acc[t] = fmaf(Gs[t][s], a, acc[t]);
    }
  }

  // epilogue
  const float* denb = gden + b * Tz + c * Sc;
#pragma unroll
  for (int t = 0; t < Sc; t++) {
    int idx = row0 + t * Hz + i;
    float ht = gPprev[idx] * acc[t];
    outp[idx] = go[idx] * __fdividef(ht, denb[t]);
  }
}

// ---------------------------------------------------------------------------
// Host launch.
// ---------------------------------------------------------------------------
extern "C" void kernel_launch(void* const* d_in, const int* in_sizes, int n_in,
                              void* d_out, int out_size) {
  const float* x = (const float*)d_in[0];
  const float* W[6];
  const float* Bb[6];

  if (n_in >= 13 && in_sizes[2] == Lz * Hz) {
    for (int j = 0; j < 6; j++) {
      W[j]  = (const float*)d_in[1 + 2 * j];
      Bb[j] = (const float*)d_in[2 + 2 * j];
    }
  } else {
    for (int j = 0; j < 6; j++) {
      W[j]  = (const float*)d_in[1 + j];
      Bb[j] = (const float*)d_in[7 + j];
    }
  }

  for (int l = 0; l < Lz; l++) {
    GemmArgs a;
    a.X = x;
    a.use_h1 = l;
    for (int j = 0; j < 6; j++) {
      a.W[j]    = W[j]  + l * Hz * Dz;
      a.bias[j] = Bb[j] + l * Hz;
    }
    gemm_act<<<dim3(BT / 64, 12), 256>>>(a);
    cum_k<<<Bz * NC, 128>>>();
    nscan_k<<<32, 32>>>();
    denom_k<<<(BT * 32) / 256, 256>>>();
    state_k<<<Bz, 1024>>>();
    out_k<<<Bz * NC, 128>>>((float*)d_out, (l == Lz - 1) ? 1 : 0);
  }
}

// round 7
// speedup vs baseline: 6.0779x; 3.3459x over previous
#include <cuda_runtime.h>
#include <math.h>

#define Bz 8
#define Tz 512
#define Dz 128
#define Hz 128
#define BT (Bz*Tz)          // 4096
#define BTH (BT*Hz)         // 524288
#define Lz 2
#define Sc 16               // chunk size
#define NC (Tz/Sc)          // 32 chunks

// ---- scratch (device globals; no allocation allowed) ----
__device__ __align__(128) float gq[BTH];
__device__ __align__(128) float gk[BTH];     // pre-scaled by 1/sqrt(H)
__device__ __align__(128) float gv[BTH];
__device__ __align__(128) float gi[BTH];     // exp(zi)
__device__ __align__(128) float gf[BTH];     // sigmoid(zf)
__device__ __align__(128) float go[BTH];     // sigmoid(zo)
__device__ __align__(128) float gh1[BTH];    // layer-1 output
__device__ __align__(128) float gden[BT];
// chunked-scan scratch
__device__ __align__(128) float gA[BTH];       // Ahat[s][i] = i*v / Pn[s]
__device__ __align__(128) float gAk[BTH];      // ikhat[s][i] = i*k / Pn[s]
__device__ __align__(128) float gPprev[BTH];   // Pn[t-1] (t=0 slot = 1/sqrt(Ptot))
__device__ __align__(128) float gsqP[Bz*NC*Hz];  // sqrt(Ptot) per (b,c,i)
__device__ __align__(128) float gPtot[Bz*NC*Hz]; // Ptot per (b,c,i)
__device__ __align__(128) float gNst[Bz*NC*Hz];  // chunk-start n
__device__ __align__(128) float gCst[Bz*NC*Hz*Hz]; // chunk-start states (16MB)

struct GemmArgs {
  const float* X;
  const float* W[6];
  const float* bias[6];
  int use_h1;
};

// ---------------------------------------------------------------------------
// Kernel 1: fused 6-way projection GEMM + activations.
// 128(n) x 64(m) tile, 256 threads, 8x4 microtile.
// Thread (tx,ty): rows n = ty*8..+7, cols m = j*16+tx (j=0..3).
// smem stride 33 -> all inner LDS broadcast & conflict-free.
// grid (BT/128, 12): blockIdx.y -> p = y>>1, mbase = (y&1)*64.
// ---------------------------------------------------------------------------
__global__ __launch_bounds__(256) void gemm_act(GemmArgs a) {
  __shared__ float As[128][33];
  __shared__ float Bs[64][33];
  const float* Xp = a.use_h1 ? gh1 : a.X;

  int tid = threadIdx.x;
  int n0 = blockIdx.x * 128;
  int by = blockIdx.y;
  int p = by >> 1;
  int mbase = (by & 1) * 64;
  const float* Wp = a.W[p];

  int tx = tid & 15, ty = tid >> 4;

  float acc[8][4];
#pragma unroll
  for (int i = 0; i < 8; i++)
#pragma unroll
    for (int j = 0; j < 4; j++) acc[i][j] = 0.f;

  for (int kk = 0; kk < Dz; kk += 32) {
    // stage X tile: 128 n x 32 k = 1024 float4 slots
#pragma unroll
    for (int s = 0; s < 4; s++) {
      int e = s * 256 + tid;
      int n = e >> 3, k4 = e & 7;
      float4 xv = *(const float4*)(Xp + (n0 + n) * Dz + kk + 4 * k4);
      As[n][4 * k4 + 0] = xv.x;
      As[n][4 * k4 + 1] = xv.y;
      As[n][4 * k4 + 2] = xv.z;
      As[n][4 * k4 + 3] = xv.w;
    }
    // stage W tile: 64 m x 32 k = 512 float4 slots
#pragma unroll
    for (int s = 0; s < 2; s++) {
      int e = s * 256 + tid;
      int m = e >> 3, k4 = e & 7;
      float4 wv = *(const float4*)(Wp + (mbase + m) * Dz + kk + 4 * k4);
      Bs[m][4 * k4 + 0] = wv.x;
      Bs[m][4 * k4 + 1] = wv.y;
      Bs[m][4 * k4 + 2] = wv.z;
      Bs[m][4 * k4 + 3] = wv.w;
    }
    __syncthreads();
#pragma unroll 4
    for (int k = 0; k < 32; k++) {
      float av[8], bv[4];
#pragma unroll
      for (int i = 0; i < 8; i++) av[i] = As[ty * 8 + i][k];
#pragma unroll
      for (int j = 0; j < 4; j++) bv[j] = Bs[j * 16 + tx][k];
#pragma unroll
      for (int i = 0; i < 8; i++)
#pragma unroll
        for (int j = 0; j < 4; j++)
          acc[i][j] = fmaf(av[i], bv[j], acc[i][j]);
    }
    __syncthreads();
  }

  float* outs;
  switch (p) {
    case 0: outs = gq; break;
    case 1: outs = gk; break;
    case 2: outs = gv; break;
    case 3: outs = gi; break;
    case 4: outs = gf; break;
    default: outs = go; break;
  }
  const float kscale = 0.08838834764831845f;  // 1/sqrt(128)
  const float* bp = a.bias[p];
#pragma unroll
  for (int i = 0; i < 8; i++) {
    int n = n0 + ty * 8 + i;
#pragma unroll
    for (int j = 0; j < 4; j++) {
      int m = mbase + j * 16 + tx;
      float val = acc[i][j] + bp[m];
      float r;
      if (p == 0)      r = val;
      else if (p == 1) r = val * kscale;
      else if (p == 2) r = val;
      else if (p == 3) r = __expf(val);
      else             r = __fdividef(1.f, 1.f + __expf(-val));
      outs[n * Hz + m] = r;
    }
  }
}

// ---------------------------------------------------------------------------
// Kernel 2: per-chunk log-decay cumsum -> Pprev / Ahat / ikhat / sqrtP / Ptot.
// Center-shifted: Pn[t] = exp(cum[t] - cum[S-1]/2); ratios are exact.
// grid = (Bz*NC), block = 128 (one i per thread).
// ---------------------------------------------------------------------------
__global__ __launch_bounds__(128) void cum_k() {
  int bc = blockIdx.x;
  int i = threadIdx.x;
  int base = bc * Sc * Hz + i;

  float lf[Sc];
  float ct = 0.f;
#pragma unroll
  for (int t = 0; t < Sc; t++) {
    float f = gf[base + t * Hz];
    float l = __logf(f);
    lf[t] = l;
    ct += l;
  }
  float sq2 = 0.5f * ct;

  gPprev[base] = __expf(-sq2);   // t=0 slot: Pn[-1] = 1/sqrt(Ptot)
  float c_run = 0.f;
#pragma unroll
  for (int t = 0; t < Sc; t++) {
    c_run += lf[t];
    float e = __expf(sq2 - c_run);
    float ii = gi[base + t * Hz];
    gA[base + t * Hz]  = ii * gv[base + t * Hz] * e;
    gAk[base + t * Hz] = ii * gk[base + t * Hz] * e;
    if (t < Sc - 1) gPprev[base + (t + 1) * Hz] = __expf(c_run - sq2);
  }
  gsqP[bc * Hz + i]  = __expf(sq2);
  gPtot[bc * Hz + i] = __expf(ct);
}

// ---------------------------------------------------------------------------
// Kernel 3: serial chunk-scan of scalar n per channel (32 steps, 1024 thr).
// n_end = Ptot*n_start + sqrtP * sum_s ikhat[s]. Stores chunk-start n.
// ---------------------------------------------------------------------------
__global__ __launch_bounds__(128) void nchunk_k() {
  int b = blockIdx.x;
  int i = threadIdx.x;
  float n = 0.f;
  for (int c = 0; c < NC; c++) {
    gNst[(b * NC + c) * Hz + i] = n;
    int rb = (b * Tz + c * Sc) * Hz;
    float s = 0.f;
#pragma unroll
    for (int t = 0; t < Sc; t++) s += gAk[rb + t * Hz + i];
    n = fmaf(gPtot[(b * NC + c) * Hz + i], n,
             gsqP[(b * NC + c) * Hz + i] * s);
  }
}

// ---------------------------------------------------------------------------
// Kernel 4: denom per (b,t), fully parallel over chunks.
// n_{t-1}[i] = Pprev[t][i]*(sqrtP*nstart[i] + sum_{s<t} ikhat[s][i]),
// den[t] = max(|n_{t-1} . q_t|, 1). grid = Bz*NC, block = 128.
// ---------------------------------------------------------------------------
__global__ __launch_bounds__(128) void nden_k() {
  __shared__ float cs[Sc][128];
  int bc = blockIdx.x;
  int i = threadIdx.x;
  int row0 = bc * Sc * Hz;

  float run = gsqP[bc * Hz + i] * gNst[bc * Hz + i];
#pragma unroll
  for (int t = 0; t < Sc; t++) {
    int idx = row0 + t * Hz + i;
    cs[t][i] = gPprev[idx] * run * gq[idx];
    run += gAk[idx];
  }
  __syncthreads();

  int w = i >> 5, lane = i & 31;
  int b = bc >> 5, c = bc & 31;
#pragma unroll
  for (int tt = 0; tt < 4; tt++) {
    int t = w * 4 + tt;
    float s = cs[t][lane] + cs[t][lane + 32] + cs[t][lane + 64] + cs[t][lane + 96];
#pragma unroll
    for (int o = 16; o; o >>= 1) s += __shfl_xor_sync(0xffffffffu, s, o);
    if (lane == 0) gden[b * Tz + c * Sc + t] = fmaxf(fabsf(s), 1.f);
  }
}

// ---------------------------------------------------------------------------
// Kernel 5: serial chunk-state scan, parallel over (b, j-group).
// grid (Bz, 16): block handles all 128 i, 8 j-columns. block = 128 (thread=i).
// Cend = Ptot_i*Cstart + sqrtP_i * sum_s Ahat[s][i]*k_s[j].
// ---------------------------------------------------------------------------
__global__ __launch_bounds__(128) void state_k() {
  __shared__ float ksm[Sc][8];
  int b = blockIdx.x;
  int j0 = blockIdx.y * 8;
  int i = threadIdx.x;

  float C[8];
#pragma unroll
  for (int m = 0; m < 8; m++) C[m] = 0.f;

  for (int c = 0; c < NC; c++) {
    // store chunk-start state
    float* dst = gCst + (((b * NC + c) * Hz + i) * Hz + j0);
    *(float4*)(dst)     = make_float4(C[0], C[1], C[2], C[3]);
    *(float4*)(dst + 4) = make_float4(C[4], C[5], C[6], C[7]);

    int rb = (b * Tz + c * Sc) * Hz;
    // stage k tile 16 x 8
    ksm[i >> 3][i & 7] = gk[rb + (i >> 3) * Hz + j0 + (i & 7)];
    __syncthreads();

    float sum[8];
#pragma unroll
    for (int m = 0; m < 8; m++) sum[m] = 0.f;
#pragma unroll
    for (int s = 0; s < Sc; s++) {
      float a_ = gA[rb + s * Hz + i];
#pragma unroll
      for (int m = 0; m < 8; m++) sum[m] = fmaf(a_, ksm[s][m], sum[m]);
    }
    float pt = gPtot[(b * NC + c) * Hz + i];
    float sp = gsqP[(b * NC + c) * Hz + i];
#pragma unroll
    for (int m = 0; m < 8; m++) C[m] = fmaf(pt, C[m], sp * sum[m]);
    __syncthreads();
  }
}

// ---------------------------------------------------------------------------
// Kernel 6: per-chunk outputs (fully parallel over (b,c)).
// h~[t][i] = Pprev[t][i] * ( sum_{s<t} G[t][s]*Ahat[s][i]
//                            + sqrtP_i * (Cstart[i,:].q_t) )
// h = o * h~ / den.  grid = Bz*NC, block = 128 (thread = i).
// ---------------------------------------------------------------------------
__global__ __launch_bounds__(128) void out_k(float* dout, int last) {
  __shared__ float qsm[Sc][132];
  __shared__ float ksm[Sc][132];
  __shared__ float Asm[Sc][128];
  __shared__ float Gs[Sc][Sc];

  int bc = blockIdx.x;
  int b = bc >> 5;
  int c = bc & 31;
  int tid = threadIdx.x;
  int row0 = bc * Sc * Hz;
  float* outp = last ? dout : gh1;

  for (int idx = tid; idx < Sc * Hz; idx += 128) {
    int t = idx >> 7, d = idx & 127;
    qsm[t][d] = gq[row0 + idx];
    ksm[t][d] = gk[row0 + idx];
    Asm[t][d] = gA[row0 + idx];
  }
  __syncthreads();

  // G[t][s] = k_s . q_t  (strict lower: s < t)
#pragma unroll
  for (int e0 = 0; e0 < 2; e0++) {
    int e = tid + e0 * 128;
    int t = e >> 4, s = e & 15;
    float gacc = 0.f;
    if (s < t) {
#pragma unroll 16
      for (int d = 0; d < Hz; d++) gacc = fmaf(ksm[s][d], qsm[t][d], gacc);
    }
    Gs[t][s] = gacc;
  }
  __syncthreads();

  int i = tid;
  float acc[Sc];
#pragma unroll
  for (int t = 0; t < Sc; t++) acc[t] = 0.f;

  // inter: CQ[t] = Cstart[i,:] . q_t
  const float4* crow = (const float4*)(gCst + (((long)bc * Hz + i) * Hz));
#pragma unroll 4
  for (int j4 = 0; j4 < 32; j4++) {
    float4 cv = crow[j4];
    int j = j4 * 4;
#pragma unroll
    for (int t = 0; t < Sc; t++) {
      acc[t] = fmaf(cv.x, qsm[t][j],     acc[t]);
      acc[t] = fmaf(cv.y, qsm[t][j + 1], acc[t]);
      acc[t] = fmaf(cv.z, qsm[t][j + 2], acc[t]);
      acc[t] = fmaf(cv.w, qsm[t][j + 3], acc[t]);
    }
  }
  float sp = gsqP[bc * Hz + i];
#pragma unroll
  for (int t = 0; t < Sc; t++) acc[t] *= sp;

  // intra: sum_{s<t} G[t][s] * Ahat[s][i]
#pragma unroll
  for (int s = 0; s < Sc - 1; s++) {
    float a = Asm[s][i];
#pragma unroll
    for (int t = 0; t < Sc; t++) {
      if (t > s) acc[t] = fmaf(Gs[t][s], a, acc[t]);
    }
  }

  // epilogue
  const float* denb = gden + b * Tz + c * Sc;
#pragma unroll
  for (int t = 0; t < Sc; t++) {
    int idx = row0 + t * Hz + i;
    float ht = gPprev[idx] * acc[t];
    outp[idx] = go[idx] * __fdividef(ht, denb[t]);
  }
}

// ---------------------------------------------------------------------------
// Host launch.
// ---------------------------------------------------------------------------
extern "C" void kernel_launch(void* const* d_in, const int* in_sizes, int n_in,
                              void* d_out, int out_size) {
  const float* x = (const float*)d_in[0];
  const float* W[6];
  const float* Bb[6];

  if (n_in >= 13 && in_sizes[2] == Lz * Hz) {
    for (int j = 0; j < 6; j++) {
      W[j]  = (const float*)d_in[1 + 2 * j];
      Bb[j] = (const float*)d_in[2 + 2 * j];
    }
  } else {
    for (int j = 0; j < 6; j++) {
      W[j]  = (const float*)d_in[1 + j];
      Bb[j] = (const float*)d_in[7 + j];
    }
  }

  for (int l = 0; l < Lz; l++) {
    GemmArgs a;
    a.X = x;
    a.use_h1 = l;
    for (int j = 0; j < 6; j++) {
      a.W[j]    = W[j]  + l * Hz * Dz;
      a.bias[j] = Bb[j] + l * Hz;
    }
    gemm_act<<<dim3(BT / 128, 12), 256>>>(a);
    cum_k<<<Bz * NC, 128>>>();
    nchunk_k<<<Bz, 128>>>();
    state_k<<<dim3(Bz, 16), 128>>>();
    nden_k<<<Bz * NC, 128>>>();
    out_k<<<Bz * NC, 128>>>((float*)d_out, (l == Lz - 1) ? 1 : 0);
  }
}

// round 8
// speedup vs baseline: 8.1502x; 1.3410x over previous
#include <cuda_runtime.h>
#include <math.h>

#define Bz 8
#define Tz 512
#define Dz 128
#define Hz 128
#define BT (Bz*Tz)          // 4096
#define BTH (BT*Hz)         // 524288
#define Lz 2
#define Sc 16               // chunk size
#define NC (Tz/Sc)          // 32 chunks

// ---- scratch (device globals; no allocation allowed) ----
__device__ __align__(128) float gq[BTH];
__device__ __align__(128) float gk[BTH];     // pre-scaled by 1/sqrt(H)
__device__ __align__(128) float gv[BTH];
__device__ __align__(128) float gi[BTH];     // exp(zi)
__device__ __align__(128) float gf[BTH];     // sigmoid(zf)
__device__ __align__(128) float go[BTH];     // sigmoid(zo)
__device__ __align__(128) float gh1[BTH];    // layer-1 output
__device__ __align__(128) float gden[BT];
// chunked-scan scratch
__device__ __align__(128) float gA[BTH];       // Ahat[s][i] = i*v / Pn[s]
__device__ __align__(128) float gAk[BTH];      // ikhat[s][i] = i*k / Pn[s]
__device__ __align__(128) float gPprev[BTH];   // Pn[t-1] (t=0 slot = 1/sqrt(Ptot))
__device__ __align__(128) float gsqP[Bz*NC*Hz];  // sqrt(Ptot) per (b,c,i)
__device__ __align__(128) float gPtot[Bz*NC*Hz]; // Ptot per (b,c,i)
__device__ __align__(128) float gNst[Bz*NC*Hz];  // chunk-start n
__device__ __align__(128) float gS[Bz*NC*Hz*Hz];   // per-chunk scaled sums, [bc][j][i]
__device__ __align__(128) float gCst[Bz*NC*Hz*Hz]; // chunk-start states, [bc][j][i]

struct GemmArgs {
  const float* X;
  const float* W[6];
  const float* bias[6];
  int use_h1;
};

// ---------------------------------------------------------------------------
// Kernel 1: fused 6-way projection GEMM + activations.
// 128(n) x 64(m) tile, 256 threads, 8x4 microtile.
// ---------------------------------------------------------------------------
__global__ __launch_bounds__(256) void gemm_act(GemmArgs a) {
  __shared__ float As[128][33];
  __shared__ float Bs[64][33];
  const float* Xp = a.use_h1 ? gh1 : a.X;

  int tid = threadIdx.x;
  int n0 = blockIdx.x * 128;
  int by = blockIdx.y;
  int p = by >> 1;
  int mbase = (by & 1) * 64;
  const float* Wp = a.W[p];

  int tx = tid & 15, ty = tid >> 4;

  float acc[8][4];
#pragma unroll
  for (int i = 0; i < 8; i++)
#pragma unroll
    for (int j = 0; j < 4; j++) acc[i][j] = 0.f;

  for (int kk = 0; kk < Dz; kk += 32) {
#pragma unroll
    for (int s = 0; s < 4; s++) {
      int e = s * 256 + tid;
      int n = e >> 3, k4 = e & 7;
      float4 xv = *(const float4*)(Xp + (n0 + n) * Dz + kk + 4 * k4);
      As[n][4 * k4 + 0] = xv.x;
      As[n][4 * k4 + 1] = xv.y;
      As[n][4 * k4 + 2] = xv.z;
      As[n][4 * k4 + 3] = xv.w;
    }
#pragma unroll
    for (int s = 0; s < 2; s++) {
      int e = s * 256 + tid;
      int m = e >> 3, k4 = e & 7;
      float4 wv = *(const float4*)(Wp + (mbase + m) * Dz + kk + 4 * k4);
      Bs[m][4 * k4 + 0] = wv.x;
      Bs[m][4 * k4 + 1] = wv.y;
      Bs[m][4 * k4 + 2] = wv.z;
      Bs[m][4 * k4 + 3] = wv.w;
    }
    __syncthreads();
#pragma unroll 4
    for (int k = 0; k < 32; k++) {
      float av[8], bv[4];
#pragma unroll
      for (int i = 0; i < 8; i++) av[i] = As[ty * 8 + i][k];
#pragma unroll
      for (int j = 0; j < 4; j++) bv[j] = Bs[j * 16 + tx][k];
#pragma unroll
      for (int i = 0; i < 8; i++)
#pragma unroll
        for (int j = 0; j < 4; j++)
          acc[i][j] = fmaf(av[i], bv[j], acc[i][j]);
    }
    __syncthreads();
  }

  float* outs;
  switch (p) {
    case 0: outs = gq; break;
    case 1: outs = gk; break;
    case 2: outs = gv; break;
    case 3: outs = gi; break;
    case 4: outs = gf; break;
    default: outs = go; break;
  }
  const float kscale = 0.08838834764831845f;  // 1/sqrt(128)
  const float* bp = a.bias[p];
#pragma unroll
  for (int i = 0; i < 8; i++) {
    int n = n0 + ty * 8 + i;
#pragma unroll
    for (int j = 0; j < 4; j++) {
      int m = mbase + j * 16 + tx;
      float val = acc[i][j] + bp[m];
      float r;
      if (p == 0)      r = val;
      else if (p == 1) r = val * kscale;
      else if (p == 2) r = val;
      else if (p == 3) r = __expf(val);
      else             r = __fdividef(1.f, 1.f + __expf(-val));
      outs[n * Hz + m] = r;
    }
  }
}

// ---------------------------------------------------------------------------
// Kernel 2: per-chunk log-decay cumsum -> Pprev / Ahat / ikhat / sqrtP / Ptot.
// ---------------------------------------------------------------------------
__global__ __launch_bounds__(128) void cum_k() {
  int bc = blockIdx.x;
  int i = threadIdx.x;
  int base = bc * Sc * Hz + i;

  float lf[Sc];
  float ct = 0.f;
#pragma unroll
  for (int t = 0; t < Sc; t++) {
    float f = gf[base + t * Hz];
    float l = __logf(f);
    lf[t] = l;
    ct += l;
  }
  float sq2 = 0.5f * ct;

  gPprev[base] = __expf(-sq2);   // t=0 slot: Pn[-1] = 1/sqrt(Ptot)
  float c_run = 0.f;
#pragma unroll
  for (int t = 0; t < Sc; t++) {
    c_run += lf[t];
    float e = __expf(sq2 - c_run);
    float ii = gi[base + t * Hz];
    gA[base + t * Hz]  = ii * gv[base + t * Hz] * e;
    gAk[base + t * Hz] = ii * gk[base + t * Hz] * e;
    if (t < Sc - 1) gPprev[base + (t + 1) * Hz] = __expf(c_run - sq2);
  }
  gsqP[bc * Hz + i]  = __expf(sq2);
  gPtot[bc * Hz + i] = __expf(ct);
}

// ---------------------------------------------------------------------------
// Kernel 3: serial chunk-scan of scalar n per channel (32 steps).
// ---------------------------------------------------------------------------
__global__ __launch_bounds__(128) void nchunk_k() {
  int b = blockIdx.x;
  int i = threadIdx.x;
  float n = 0.f;
  for (int c = 0; c < NC; c++) {
    gNst[(b * NC + c) * Hz + i] = n;
    int rb = (b * Tz + c * Sc) * Hz;
    float s = 0.f;
#pragma unroll
    for (int t = 0; t < Sc; t++) s += gAk[rb + t * Hz + i];
    n = fmaf(gPtot[(b * NC + c) * Hz + i], n,
             gsqP[(b * NC + c) * Hz + i] * s);
  }
}

// ---------------------------------------------------------------------------
// Kernel 4: denom per (b,t), fully parallel over chunks.
// ---------------------------------------------------------------------------
__global__ __launch_bounds__(128) void nden_k() {
  __shared__ float cs[Sc][128];
  int bc = blockIdx.x;
  int i = threadIdx.x;
  int row0 = bc * Sc * Hz;

  float run = gsqP[bc * Hz + i] * gNst[bc * Hz + i];
#pragma unroll
  for (int t = 0; t < Sc; t++) {
    int idx = row0 + t * Hz + i;
    cs[t][i] = gPprev[idx] * run * gq[idx];
    run += gAk[idx];
  }
  __syncthreads();

  int w = i >> 5, lane = i & 31;
  int b = bc >> 5, c = bc & 31;
#pragma unroll
  for (int tt = 0; tt < 4; tt++) {
    int t = w * 4 + tt;
    float s = cs[t][lane] + cs[t][lane + 32] + cs[t][lane + 64] + cs[t][lane + 96];
#pragma unroll
    for (int o = 16; o; o >>= 1) s += __shfl_xor_sync(0xffffffffu, s, o);
    if (lane == 0) gden[b * Tz + c * Sc + t] = fmaxf(fabsf(s), 1.f);
  }
}

// ---------------------------------------------------------------------------
// Kernel 5a: per-chunk scaled local sums (fully parallel).
// S'[bc][j][i] = sqrtP_i * sum_s Ahat[s][i] * k_s[j].
// grid (Bz*NC, 8): j-tile of 16. block = 128 (thread = i).
// ---------------------------------------------------------------------------
__global__ __launch_bounds__(128) void sum_k() {
  __shared__ float ksm[Sc][16];
  int bc = blockIdx.x;
  int j0 = blockIdx.y * 16;
  int i = threadIdx.x;
  int rb = bc * Sc * Hz;

#pragma unroll
  for (int e = 0; e < 2; e++) {
    int idx = i + e * 128;
    ksm[idx >> 4][idx & 15] = gk[rb + (idx >> 4) * Hz + j0 + (idx & 15)];
  }
  __syncthreads();

  float acc[16];
#pragma unroll
  for (int jj = 0; jj < 16; jj++) acc[jj] = 0.f;
#pragma unroll
  for (int s = 0; s < Sc; s++) {
    float a = gA[rb + s * Hz + i];
#pragma unroll
    for (int jj = 0; jj < 16; jj++) acc[jj] = fmaf(a, ksm[s][jj], acc[jj]);
  }
  float sp = gsqP[bc * Hz + i];
  long ob = ((long)bc * Hz + j0) * Hz + i;
#pragma unroll
  for (int jj = 0; jj < 16; jj++) gS[ob + jj * Hz] = sp * acc[jj];
}

// ---------------------------------------------------------------------------
// Kernel 5b: streaming chunk-state scan (serial over c, parallel over b,i,j).
// C[j][i] at chunk start stored to gCst; C = Ptot_i * C + S'[c][j][i].
// grid = Bz*Hz (block -> (b,j)), block = 128 (thread = i). All accesses coalesced.
// ---------------------------------------------------------------------------
__global__ __launch_bounds__(128) void combine_k() {
  int b = blockIdx.x >> 7;
  int j = blockIdx.x & 127;
  int i = threadIdx.x;
  long base = ((long)b * NC * Hz + j) * Hz + i;   // c stride = Hz*Hz
  int pbase = b * NC * Hz + i;                    // c stride = Hz

  float C = 0.f;
  for (int c = 0; c < NC; c += 4) {
    float s0 = gS[base + (long)(c + 0) * Hz * Hz];
    float s1 = gS[base + (long)(c + 1) * Hz * Hz];
    float s2 = gS[base + (long)(c + 2) * Hz * Hz];
    float s3 = gS[base + (long)(c + 3) * Hz * Hz];
    float p0 = gPtot[pbase + (c + 0) * Hz];
    float p1 = gPtot[pbase + (c + 1) * Hz];
    float p2 = gPtot[pbase + (c + 2) * Hz];
    float p3 = gPtot[pbase + (c + 3) * Hz];
    gCst[base + (long)(c + 0) * Hz * Hz] = C;
    C = fmaf(p0, C, s0);
    gCst[base + (long)(c + 1) * Hz * Hz] = C;
    C = fmaf(p1, C, s1);
    gCst[base + (long)(c + 2) * Hz * Hz] = C;
    C = fmaf(p2, C, s2);
    gCst[base + (long)(c + 3) * Hz * Hz] = C;
    C = fmaf(p3, C, s3);
  }
}

// ---------------------------------------------------------------------------
// Kernel 6: per-chunk outputs (fully parallel over (b,c)).
// h~[t][i] = Pprev[t][i] * ( sum_{s<t} G[t][s]*Ahat[s][i]
//                            + sqrtP_i * (Cstart[i,:].q_t) )
// gCst layout [bc][j][i]: staged via smem in 16-row batches (coalesced).
// ---------------------------------------------------------------------------
__global__ __launch_bounds__(128) void out_k(float* dout, int last) {
  __shared__ float qsm[Sc][132];
  __shared__ float ksm[Sc][132];
  __shared__ float Asm[Sc][128];
  __shared__ float Gs[Sc][Sc];
  __shared__ float Csm[16][128];

  int bc = blockIdx.x;
  int b = bc >> 5;
  int c = bc & 31;
  int tid = threadIdx.x;
  int row0 = bc * Sc * Hz;
  float* outp = last ? dout : gh1;

  for (int idx = tid; idx < Sc * Hz; idx += 128) {
    int t = idx >> 7, d = idx & 127;
    qsm[t][d] = gq[row0 + idx];
    ksm[t][d] = gk[row0 + idx];
    Asm[t][d] = gA[row0 + idx];
  }
  __syncthreads();

  // G[t][s] = k_s . q_t (strict lower; zero elsewhere)
#pragma unroll
  for (int e0 = 0; e0 < 2; e0++) {
    int e = tid + e0 * 128;
    int t = e >> 4, s = e & 15;
    float gacc = 0.f;
    if (s < t) {
#pragma unroll 8
      for (int d4 = 0; d4 < 32; d4++) {
        float4 kk = *(const float4*)&ksm[s][4 * d4];
        float4 qq = *(const float4*)&qsm[t][4 * d4];
        gacc = fmaf(kk.x, qq.x, gacc);
        gacc = fmaf(kk.y, qq.y, gacc);
        gacc = fmaf(kk.z, qq.z, gacc);
        gacc = fmaf(kk.w, qq.w, gacc);
      }
    }
    Gs[t][s] = gacc;
  }
  __syncthreads();

  int i = tid;
  float acc[Sc];
#pragma unroll
  for (int t = 0; t < Sc; t++) acc[t] = 0.f;

  // inter: acc[t] += Cstart[i][j] * q_t[j], staged in 16-j batches
  for (int j0 = 0; j0 < Hz; j0 += 16) {
#pragma unroll
    for (int e = 0; e < 16; e++) {
      Csm[e][tid] = gCst[((long)bc * Hz + j0 + e) * Hz + tid];
    }
    __syncthreads();
    float cj[16];
#pragma unroll
    for (int jj = 0; jj < 16; jj++) cj[jj] = Csm[jj][i];
#pragma unroll
    for (int t = 0; t < Sc; t++) {
#pragma unroll
      for (int jj4 = 0; jj4 < 4; jj4++) {
        float4 qq = *(const float4*)&qsm[t][j0 + 4 * jj4];
        acc[t] = fmaf(cj[4 * jj4 + 0], qq.x, acc[t]);
        acc[t] = fmaf(cj[4 * jj4 + 1], qq.y, acc[t]);
        acc[t] = fmaf(cj[4 * jj4 + 2], qq.z, acc[t]);
        acc[t] = fmaf(cj[4 * jj4 + 3], qq.w, acc[t]);
      }
    }
    __syncthreads();
  }
  float sp = gsqP[bc * Hz + i];
#pragma unroll
  for (int t = 0; t < Sc; t++) acc[t] *= sp;

  // intra: acc[t] += sum_s G[t][s] * Ahat[s][i]  (G zero-filled above diag)
#pragma unroll
  for (int s4 = 0; s4 < 4; s4++) {
    float a0 = Asm[4 * s4 + 0][i];
    float a1 = Asm[4 * s4 + 1][i];
    float a2 = Asm[4 * s4 + 2][i];
    float a3 = Asm[4 * s4 + 3][i];
#pragma unroll
    for (int t = 0; t < Sc; t++) {
      float4 g = *(const float4*)&Gs[t][4 * s4];
      acc[t] = fmaf(g.x, a0, acc[t]);
      acc[t] = fmaf(g.y, a1, acc[t]);
      acc[t] = fmaf(g.z, a2, acc[t]);
      acc[t] = fmaf(g.w, a3, acc[t]);
    }
  }

  // epilogue
  const float* denb = gden + b * Tz + c * Sc;
#pragma unroll
  for (int t = 0; t < Sc; t++) {
    int idx = row0 + t * Hz + i;
    float ht = gPprev[idx] * acc[t];
    outp[idx] = go[idx] * __fdividef(ht, denb[t]);
  }
}

// ---------------------------------------------------------------------------
// Host launch.
// ---------------------------------------------------------------------------
extern "C" void kernel_launch(void* const* d_in, const int* in_sizes, int n_in,
                              void* d_out, int out_size) {
  const float* x = (const float*)d_in[0];
  const float* W[6];
  const float* Bb[6];

  if (n_in >= 13 && in_sizes[2] == Lz * Hz) {
    for (int j = 0; j < 6; j++) {
      W[j]  = (const float*)d_in[1 + 2 * j];
      Bb[j] = (const float*)d_in[2 + 2 * j];
    }
  } else {
    for (int j = 0; j < 6; j++) {
      W[j]  = (const float*)d_in[1 + j];
      Bb[j] = (const float*)d_in[7 + j];
    }
  }

  for (int l = 0; l < Lz; l++) {
    GemmArgs a;
    a.X = x;
    a.use_h1 = l;
    for (int j = 0; j < 6; j++) {
      a.W[j]    = W[j]  + l * Hz * Dz;
      a.bias[j] = Bb[j] + l * Hz;
    }
    gemm_act<<<dim3(BT / 128, 12), 256>>>(a);
    cum_k<<<Bz * NC, 128>>>();
    nchunk_k<<<Bz, 128>>>();
    sum_k<<<dim3(Bz * NC, 8), 128>>>();
    combine_k<<<Bz * Hz, 128>>>();
    nden_k<<<Bz * NC, 128>>>();
    out_k<<<Bz * NC, 128>>>((float*)d_out, (l == Lz - 1) ? 1 : 0);
  }
}

// round 9
// speedup vs baseline: 8.5284x; 1.0464x over previous
#include <cuda_runtime.h>
#include <math.h>

#define Bz 8
#define Tz 512
#define Dz 128
#define Hz 128
#define BT (Bz*Tz)          // 4096
#define BTH (BT*Hz)         // 524288
#define Lz 2
#define Sc 16               // chunk size
#define NC (Tz/Sc)          // 32 chunks

// ---- scratch (device globals; no allocation allowed) ----
__device__ __align__(128) float gq[BTH];
__device__ __align__(128) float gk[BTH];     // pre-scaled by 1/sqrt(H)
__device__ __align__(128) float gv[BTH];
__device__ __align__(128) float gi[BTH];     // exp(zi)
__device__ __align__(128) float gf[BTH];     // sigmoid(zf)
__device__ __align__(128) float go[BTH];     // sigmoid(zo)
__device__ __align__(128) float gh1[BTH];    // layer-1 output
__device__ __align__(128) float gden[BT];
// chunked-scan scratch
__device__ __align__(128) float gA[BTH];       // Ahat[s][i] = i*v / Pn[s]
__device__ __align__(128) float gAk[BTH];      // ikhat[s][i] = i*k / Pn[s]
__device__ __align__(128) float gPprev[BTH];   // Pn[t-1] (t=0 slot = 1/sqrt(Ptot))
__device__ __align__(128) float gsqP[Bz*NC*Hz];  // sqrt(Ptot) per (b,c,i)
__device__ __align__(128) float gPtot[Bz*NC*Hz]; // Ptot per (b,c,i)
__device__ __align__(128) float gNst[Bz*NC*Hz];  // chunk-start n
__device__ __align__(128) float gS[Bz*NC*Hz*Hz];   // per-chunk scaled sums, [bc][j][i]
__device__ __align__(128) float gCst[Bz*NC*Hz*Hz]; // chunk-start states, [bc][j][i]

struct GemmArgs {
  const float* X;
  const float* W[6];
  const float* bias[6];
  int use_h1;
};

// ---------------------------------------------------------------------------
// Kernel 1: fused 6-way projection GEMM + activations.
// v3: 128(n) x 128(m) tile, 256 threads, 8x8 microtile, grid (32, 6).
// Thread (tx,ty): rows n = ty*8+i, cols m = jj*16+tx.
// ---------------------------------------------------------------------------
__global__ __launch_bounds__(256, 2) void gemm_act(GemmArgs a) {
  __shared__ float As[128][33];
  __shared__ float Bs[128][33];
  const float* Xp = a.use_h1 ? gh1 : a.X;

  int tid = threadIdx.x;
  int n0 = blockIdx.x * 128;
  int p = blockIdx.y;
  const float* Wp = a.W[p];

  int tx = tid & 15, ty = tid >> 4;

  float acc[8][8];
#pragma unroll
  for (int i = 0; i < 8; i++)
#pragma unroll
    for (int j = 0; j < 8; j++) acc[i][j] = 0.f;

  for (int kk = 0; kk < Dz; kk += 32) {
#pragma unroll
    for (int s = 0; s < 4; s++) {
      int e = s * 256 + tid;
      int n = e >> 3, k4 = e & 7;
      float4 xv = *(const float4*)(Xp + (n0 + n) * Dz + kk + 4 * k4);
      As[n][4 * k4 + 0] = xv.x;
      As[n][4 * k4 + 1] = xv.y;
      As[n][4 * k4 + 2] = xv.z;
      As[n][4 * k4 + 3] = xv.w;
      float4 wv = *(const float4*)(Wp + n * Dz + kk + 4 * k4);
      Bs[n][4 * k4 + 0] = wv.x;
      Bs[n][4 * k4 + 1] = wv.y;
      Bs[n][4 * k4 + 2] = wv.z;
      Bs[n][4 * k4 + 3] = wv.w;
    }
    __syncthreads();
#pragma unroll 2
    for (int k = 0; k < 32; k++) {
      float av[8], bv[8];
#pragma unroll
      for (int i = 0; i < 8; i++) av[i] = As[ty * 8 + i][k];
#pragma unroll
      for (int j = 0; j < 8; j++) bv[j] = Bs[j * 16 + tx][k];
#pragma unroll
      for (int i = 0; i < 8; i++)
#pragma unroll
        for (int j = 0; j < 8; j++)
          acc[i][j] = fmaf(av[i], bv[j], acc[i][j]);
    }
    __syncthreads();
  }

  float* outs;
  switch (p) {
    case 0: outs = gq; break;
    case 1: outs = gk; break;
    case 2: outs = gv; break;
    case 3: outs = gi; break;
    case 4: outs = gf; break;
    default: outs = go; break;
  }
  const float kscale = 0.08838834764831845f;  // 1/sqrt(128)
  const float* bp = a.bias[p];
#pragma unroll
  for (int i = 0; i < 8; i++) {
    int n = n0 + ty * 8 + i;
#pragma unroll
    for (int j = 0; j < 8; j++) {
      int m = j * 16 + tx;
      float val = acc[i][j] + bp[m];
      float r;
      if (p == 0)      r = val;
      else if (p == 1) r = val * kscale;
      else if (p == 2) r = val;
      else if (p == 3) r = __expf(val);
      else             r = __fdividef(1.f, 1.f + __expf(-val));
      outs[n * Hz + m] = r;
    }
  }
}

// ---------------------------------------------------------------------------
// Kernel 2: per-chunk log-decay cumsum -> Pprev / Ahat / ikhat / sqrtP / Ptot.
// ---------------------------------------------------------------------------
__global__ __launch_bounds__(128) void cum_k() {
  int bc = blockIdx.x;
  int i = threadIdx.x;
  int base = bc * Sc * Hz + i;

  float lf[Sc];
  float ct = 0.f;
#pragma unroll
  for (int t = 0; t < Sc; t++) {
    float f = gf[base + t * Hz];
    float l = __logf(f);
    lf[t] = l;
    ct += l;
  }
  float sq2 = 0.5f * ct;

  gPprev[base] = __expf(-sq2);   // t=0 slot: Pn[-1] = 1/sqrt(Ptot)
  float c_run = 0.f;
#pragma unroll
  for (int t = 0; t < Sc; t++) {
    c_run += lf[t];
    float e = __expf(sq2 - c_run);
    float ii = gi[base + t * Hz];
    gA[base + t * Hz]  = ii * gv[base + t * Hz] * e;
    gAk[base + t * Hz] = ii * gk[base + t * Hz] * e;
    if (t < Sc - 1) gPprev[base + (t + 1) * Hz] = __expf(c_run - sq2);
  }
  gsqP[bc * Hz + i]  = __expf(sq2);
  gPtot[bc * Hz + i] = __expf(ct);
}

// ---------------------------------------------------------------------------
// Kernel 3: serial chunk-scan of scalar n per channel (32 steps).
// ---------------------------------------------------------------------------
__global__ __launch_bounds__(128) void nchunk_k() {
  int b = blockIdx.x;
  int i = threadIdx.x;
  float n = 0.f;
  for (int c = 0; c < NC; c++) {
    gNst[(b * NC + c) * Hz + i] = n;
    int rb = (b * Tz + c * Sc) * Hz;
    float s = 0.f;
#pragma unroll
    for (int t = 0; t < Sc; t++) s += gAk[rb + t * Hz + i];
    n = fmaf(gPtot[(b * NC + c) * Hz + i], n,
             gsqP[(b * NC + c) * Hz + i] * s);
  }
}

// ---------------------------------------------------------------------------
// Kernel 4: denom per (b,t), fully parallel over chunks.
// ---------------------------------------------------------------------------
__global__ __launch_bounds__(128) void nden_k() {
  __shared__ float cs[Sc][128];
  int bc = blockIdx.x;
  int i = threadIdx.x;
  int row0 = bc * Sc * Hz;

  float run = gsqP[bc * Hz + i] * gNst[bc * Hz + i];
#pragma unroll
  for (int t = 0; t < Sc; t++) {
    int idx = row0 + t * Hz + i;
    cs[t][i] = gPprev[idx] * run * gq[idx];
    run += gAk[idx];
  }
  __syncthreads();

  int w = i >> 5, lane = i & 31;
  int b = bc >> 5, c = bc & 31;
#pragma unroll
  for (int tt = 0; tt < 4; tt++) {
    int t = w * 4 + tt;
    float s = cs[t][lane] + cs[t][lane + 32] + cs[t][lane + 64] + cs[t][lane + 96];
#pragma unroll
    for (int o = 16; o; o >>= 1) s += __shfl_xor_sync(0xffffffffu, s, o);
    if (lane == 0) gden[b * Tz + c * Sc + t] = fmaxf(fabsf(s), 1.f);
  }
}

// ---------------------------------------------------------------------------
// Kernel 5a: per-chunk scaled local sums (fully parallel).
// S'[bc][j][i] = sqrtP_i * sum_s Ahat[s][i] * k_s[j].
// ---------------------------------------------------------------------------
__global__ __launch_bounds__(128) void sum_k() {
  __shared__ float ksm[Sc][16];
  int bc = blockIdx.x;
  int j0 = blockIdx.y * 16;
  int i = threadIdx.x;
  int rb = bc * Sc * Hz;

#pragma unroll
  for (int e = 0; e < 2; e++) {
    int idx = i + e * 128;
    ksm[idx >> 4][idx & 15] = gk[rb + (idx >> 4) * Hz + j0 + (idx & 15)];
  }
  __syncthreads();

  float acc[16];
#pragma unroll
  for (int jj = 0; jj < 16; jj++) acc[jj] = 0.f;
#pragma unroll
  for (int s = 0; s < Sc; s++) {
    float a = gA[rb + s * Hz + i];
#pragma unroll
    for (int jj = 0; jj < 16; jj++) acc[jj] = fmaf(a, ksm[s][jj], acc[jj]);
  }
  float sp = gsqP[bc * Hz + i];
  long ob = ((long)bc * Hz + j0) * Hz + i;
#pragma unroll
  for (int jj = 0; jj < 16; jj++) gS[ob + jj * Hz] = sp * acc[jj];
}

// ---------------------------------------------------------------------------
// Kernel 5b: streaming chunk-state scan (serial over c, parallel over b,i,j).
// ---------------------------------------------------------------------------
__global__ __launch_bounds__(128) void combine_k() {
  int b = blockIdx.x >> 7;
  int j = blockIdx.x & 127;
  int i = threadIdx.x;
  long base = ((long)b * NC * Hz + j) * Hz + i;   // c stride = Hz*Hz
  int pbase = b * NC * Hz + i;                    // c stride = Hz

  float C = 0.f;
  for (int c = 0; c < NC; c += 4) {
    float s0 = gS[base + (long)(c + 0) * Hz * Hz];
    float s1 = gS[base + (long)(c + 1) * Hz * Hz];
    float s2 = gS[base + (long)(c + 2) * Hz * Hz];
    float s3 = gS[base + (long)(c + 3) * Hz * Hz];
    float p0 = gPtot[pbase + (c + 0) * Hz];
    float p1 = gPtot[pbase + (c + 1) * Hz];
    float p2 = gPtot[pbase + (c + 2) * Hz];
    float p3 = gPtot[pbase + (c + 3) * Hz];
    gCst[base + (long)(c + 0) * Hz * Hz] = C;
    C = fmaf(p0, C, s0);
    gCst[base + (long)(c + 1) * Hz * Hz] = C;
    C = fmaf(p1, C, s1);
    gCst[base + (long)(c + 2) * Hz * Hz] = C;
    C = fmaf(p2, C, s2);
    gCst[base + (long)(c + 3) * Hz * Hz] = C;
    C = fmaf(p3, C, s3);
  }
}

// ---------------------------------------------------------------------------
// Kernel 6: per-chunk outputs. gCst [bc][j][i] read directly (coalesced).
// ---------------------------------------------------------------------------
__global__ __launch_bounds__(128) void out_k(float* dout, int last) {
  __shared__ float qsm[Sc][132];
  __shared__ float ksm[Sc][132];
  __shared__ float Asm[Sc][128];
  __shared__ float Gs[Sc][Sc];

  int bc = blockIdx.x;
  int b = bc >> 5;
  int c = bc & 31;
  int tid = threadIdx.x;
  int row0 = bc * Sc * Hz;
  float* outp = last ? dout : gh1;

  for (int idx = tid; idx < Sc * Hz; idx += 128) {
    int t = idx >> 7, d = idx & 127;
    qsm[t][d] = gq[row0 + idx];
    ksm[t][d] = gk[row0 + idx];
    Asm[t][d] = gA[row0 + idx];
  }
  __syncthreads();

  // G[t][s] = k_s . q_t (strict lower; zero elsewhere)
#pragma unroll
  for (int e0 = 0; e0 < 2; e0++) {
    int e = tid + e0 * 128;
    int t = e >> 4, s = e & 15;
    float gacc = 0.f;
    if (s < t) {
#pragma unroll 8
      for (int d4 = 0; d4 < 32; d4++) {
        float4 kk = *(const float4*)&ksm[s][4 * d4];
        float4 qq = *(const float4*)&qsm[t][4 * d4];
        gacc = fmaf(kk.x, qq.x, gacc);
        gacc = fmaf(kk.y, qq.y, gacc);
        gacc = fmaf(kk.z, qq.z, gacc);
        gacc = fmaf(kk.w, qq.w, gacc);
      }
    }
    Gs[t][s] = gacc;
  }
  __syncthreads();

  int i = tid;
  float acc[Sc];
#pragma unroll
  for (int t = 0; t < Sc; t++) acc[t] = 0.f;

  // inter: acc[t] += Cstart[i][j] * q_t[j]; direct coalesced LDG, 16-j batches
  const float* cbase = gCst + (long)bc * Hz * Hz + i;
  for (int j0 = 0; j0 < Hz; j0 += 16) {
    float cj[16];
#pragma unroll
    for (int jj = 0; jj < 16; jj++) cj[jj] = cbase[(j0 + jj) * Hz];
#pragma unroll
    for (int t = 0; t < Sc; t++) {
#pragma unroll
      for (int jj4 = 0; jj4 < 4; jj4++) {
        float4 qq = *(const float4*)&qsm[t][j0 + 4 * jj4];
        acc[t] = fmaf(cj[4 * jj4 + 0], qq.x, acc[t]);
        acc[t] = fmaf(cj[4 * jj4 + 1], qq.y, acc[t]);
        acc[t] = fmaf(cj[4 * jj4 + 2], qq.z, acc[t]);
        acc[t] = fmaf(cj[4 * jj4 + 3], qq.w, acc[t]);
      }
    }
  }
  float sp = gsqP[bc * Hz + i];
#pragma unroll
  for (int t = 0; t < Sc; t++) acc[t] *= sp;

  // intra: acc[t] += sum_s G[t][s] * Ahat[s][i]
#pragma unroll
  for (int s4 = 0; s4 < 4; s4++) {
    float a0 = Asm[4 * s4 + 0][i];
    float a1 = Asm[4 * s4 + 1][i];
    float a2 = Asm[4 * s4 + 2][i];
    float a3 = Asm[4 * s4 + 3][i];
#pragma unroll
    for (int t = 0; t < Sc; t++) {
      float4 g = *(const float4*)&Gs[t][4 * s4];
      acc[t] = fmaf(g.x, a0, acc[t]);
      acc[t] = fmaf(g.y, a1, acc[t]);
      acc[t] = fmaf(g.z, a2, acc[t]);
      acc[t] = fmaf(g.w, a3, acc[t]);
    }
  }

  // epilogue
  const float* denb = gden + b * Tz + c * Sc;
#pragma unroll
  for (int t = 0; t < Sc; t++) {
    int idx = row0 + t * Hz + i;
    float ht = gPprev[idx] * acc[t];
    outp[idx] = go[idx] * __fdividef(ht, denb[t]);
  }
}

// ---------------------------------------------------------------------------
// Host launch. Two-stream fork (nchunk->nden || sum->combine), event-joined;
// fully graph-capturable (events/streams created once, host-side only).
// ---------------------------------------------------------------------------
extern "C" void kernel_launch(void* const* d_in, const int* in_sizes, int n_in,
                              void* d_out, int out_size) {
  static cudaStream_t s2 = nullptr;
  static cudaEvent_t evFork = nullptr, evJoin = nullptr;
  if (s2 == nullptr) {
    cudaStreamCreateWithFlags(&s2, cudaStreamNonBlocking);
    cudaEventCreateWithFlags(&evFork, cudaEventDisableTiming);
    cudaEventCreateWithFlags(&evJoin, cudaEventDisableTiming);
  }

  const float* x = (const float*)d_in[0];
  const float* W[6];
  const float* Bb[6];

  if (n_in >= 13 && in_sizes[2] == Lz * Hz) {
    for (int j = 0; j < 6; j++) {
      W[j]  = (const float*)d_in[1 + 2 * j];
      Bb[j] = (const float*)d_in[2 + 2 * j];
    }
  } else {
    for (int j = 0; j < 6; j++) {
      W[j]  = (const float*)d_in[1 + j];
      Bb[j] = (const float*)d_in[7 + j];
    }
  }

  for (int l = 0; l < Lz; l++) {
    GemmArgs a;
    a.X = x;
    a.use_h1 = l;
    for (int j = 0; j < 6; j++) {
      a.W[j]    = W[j]  + l * Hz * Dz;
      a.bias[j] = Bb[j] + l * Hz;
    }
    gemm_act<<<dim3(BT / 128, 6), 256>>>(a);
    cum_k<<<Bz * NC, 128>>>();

    // fork: n-path on s2, C-path on main stream
    cudaEventRecord(evFork, 0);
    cudaStreamWaitEvent(s2, evFork, 0);
    nchunk_k<<<Bz, 128, 0, s2>>>();
    nden_k<<<Bz * NC, 128, 0, s2>>>();
    cudaEventRecord(evJoin, s2);

    sum_k<<<dim3(Bz * NC, 8), 128>>>();
    combine_k<<<Bz * Hz, 128>>>();

    cudaStreamWaitEvent(0, evJoin, 0);
    out_k<<<Bz * NC, 128>>>((float*)d_out, (l == Lz - 1) ? 1 : 0);
  }
}

// round 10
// speedup vs baseline: 9.2401x; 1.0835x over previous
#include <cuda_runtime.h>
#include <math.h>

#define Bz 8
#define Tz 512
#define Dz 128
#define Hz 128
#define BT (Bz*Tz)          // 4096
#define BTH (BT*Hz)         // 524288
#define Lz 2
#define Sc 16               // chunk size
#define NC (Tz/Sc)          // 32 chunks

// ---- scratch (device globals; no allocation allowed) ----
__device__ __align__(128) float gq[BTH];
__device__ __align__(128) float gk[BTH];     // pre-scaled by 1/sqrt(H)
__device__ __align__(128) float gv[BTH];
__device__ __align__(128) float gi[BTH];     // exp(zi)
__device__ __align__(128) float gf[BTH];     // sigmoid(zf)
__device__ __align__(128) float go[BTH];     // sigmoid(zo)
__device__ __align__(128) float gh1[BTH];    // layer-1 output
// chunked-scan scratch
__device__ __align__(128) float gA[BTH];       // Ahat[s][i] = i*v / Pn[s]
__device__ __align__(128) float gAk[BTH];      // ikhat[s][i] = i*k / Pn[s]
__device__ __align__(128) float gPprev[BTH];   // Pn[t-1] (t=0 slot = 1/sqrt(Ptot))
__device__ __align__(128) float gsqP[Bz*NC*Hz];  // sqrt(Ptot) per (b,c,i)
__device__ __align__(128) float gPtot[Bz*NC*Hz]; // Ptot per (b,c,i)
__device__ __align__(128) float gNst[Bz*NC*Hz];  // chunk-start n
__device__ __align__(128) float gS[Bz*NC*Hz*Hz];   // per-chunk scaled sums, [bc][j][i]
__device__ __align__(128) float gCst[Bz*NC*Hz*Hz]; // chunk-start states, [bc][j][i]

struct GemmArgs {
  const float* X;
  const float* W[6];
  const float* bias[6];
  int use_h1;
};

// ---------------------------------------------------------------------------
// Kernel 1: fused 6-way projection GEMM + activations.
// 128x128 tile, 256 threads, 8x8 microtile, grid (32, 6).
// v4: register-prefetch double buffering of the k-tiles.
// ---------------------------------------------------------------------------
__global__ __launch_bounds__(256, 2) void gemm_act(GemmArgs a) {
  __shared__ float As[128][33];
  __shared__ float Bs[128][33];
  const float* Xp = a.use_h1 ? gh1 : a.X;

  int tid = threadIdx.x;
  int n0 = blockIdx.x * 128;
  int p = blockIdx.y;
  const float* Wp = a.W[p];

  int tx = tid & 15, ty = tid >> 4;

  float acc[8][8];
#pragma unroll
  for (int i = 0; i < 8; i++)
#pragma unroll
    for (int j = 0; j < 8; j++) acc[i][j] = 0.f;

  float4 xr[4], wr[4];
#pragma unroll
  for (int s = 0; s < 4; s++) {
    int e = s * 256 + tid;
    int n = e >> 3, k4 = e & 7;
    xr[s] = *(const float4*)(Xp + (n0 + n) * Dz + 4 * k4);
    wr[s] = *(const float4*)(Wp + n * Dz + 4 * k4);
  }

  for (int it = 0; it < 4; it++) {
#pragma unroll
    for (int s = 0; s < 4; s++) {
      int e = s * 256 + tid;
      int n = e >> 3, k4 = e & 7;
      As[n][4 * k4 + 0] = xr[s].x;
      As[n][4 * k4 + 1] = xr[s].y;
      As[n][4 * k4 + 2] = xr[s].z;
      As[n][4 * k4 + 3] = xr[s].w;
      Bs[n][4 * k4 + 0] = wr[s].x;
      Bs[n][4 * k4 + 1] = wr[s].y;
      Bs[n][4 * k4 + 2] = wr[s].z;
      Bs[n][4 * k4 + 3] = wr[s].w;
    }
    __syncthreads();
    if (it < 3) {
      int kk = (it + 1) * 32;
#pragma unroll
      for (int s = 0; s < 4; s++) {
        int e = s * 256 + tid;
        int n = e >> 3, k4 = e & 7;
        xr[s] = *(const float4*)(Xp + (n0 + n) * Dz + kk + 4 * k4);
        wr[s] = *(const float4*)(Wp + n * Dz + kk + 4 * k4);
      }
    }
#pragma unroll 2
    for (int k = 0; k < 32; k++) {
      float av[8], bv[8];
#pragma unroll
      for (int i = 0; i < 8; i++) av[i] = As[ty * 8 + i][k];
#pragma unroll
      for (int j = 0; j < 8; j++) bv[j] = Bs[j * 16 + tx][k];
#pragma unroll
      for (int i = 0; i < 8; i++)
#pragma unroll
        for (int j = 0; j < 8; j++)
          acc[i][j] = fmaf(av[i], bv[j], acc[i][j]);
    }
    __syncthreads();
  }

  float* outs;
  switch (p) {
    case 0: outs = gq; break;
    case 1: outs = gk; break;
    case 2: outs = gv; break;
    case 3: outs = gi; break;
    case 4: outs = gf; break;
    default: outs = go; break;
  }
  const float kscale = 0.08838834764831845f;  // 1/sqrt(128)
  const float* bp = a.bias[p];
#pragma unroll
  for (int i = 0; i < 8; i++) {
    int n = n0 + ty * 8 + i;
#pragma unroll
    for (int j = 0; j < 8; j++) {
      int m = j * 16 + tx;
      float val = acc[i][j] + bp[m];
      float r;
      if (p == 0)      r = val;
      else if (p == 1) r = val * kscale;
      else if (p == 2) r = val;
      else if (p == 3) r = __expf(val);
      else             r = __fdividef(1.f, 1.f + __expf(-val));
      outs[n * Hz + m] = r;
    }
  }
}

// ---------------------------------------------------------------------------
// Kernel 2: fused per-chunk cumsum + local state sums.
// Phase A (cum): log-f cumsum -> Pprev/Ahat/ikhat/sqrtP/Ptot, Ahat kept in regs.
// Phase B (sum): S'[bc][j][i] = sqrtP_i * sum_s Ahat[s][i]*k_s[j], k staged in smem.
// grid = Bz*NC, block = 128 (thread = i).
// ---------------------------------------------------------------------------
__global__ __launch_bounds__(128) void cumsum_k() {
  __shared__ float ksm[Sc][128];
  int bc = blockIdx.x;
  int i = threadIdx.x;
  int base = bc * Sc * Hz + i;

  float lf[Sc];
  float ct = 0.f;
#pragma unroll
  for (int t = 0; t < Sc; t++) {
    float f = gf[base + t * Hz];
    float l = __logf(f);
    lf[t] = l;
    ct += l;
  }
  float sq2 = 0.5f * ct;

  gPprev[base] = __expf(-sq2);   // t=0 slot: Pn[-1] = 1/sqrt(Ptot)
  float Areg[Sc];
  float c_run = 0.f;
#pragma unroll
  for (int t = 0; t < Sc; t++) {
    c_run += lf[t];
    float e = __expf(sq2 - c_run);
    float ii = gi[base + t * Hz];
    float kk = gk[base + t * Hz];
    float av = ii * gv[base + t * Hz] * e;
    Areg[t] = av;
    gA[base + t * Hz]  = av;
    gAk[base + t * Hz] = ii * kk * e;
    ksm[t][i] = kk;
    if (t < Sc - 1) gPprev[base + (t + 1) * Hz] = __expf(c_run - sq2);
  }
  float sp = __expf(sq2);
  gsqP[bc * Hz + i]  = sp;
  gPtot[bc * Hz + i] = __expf(ct);
  __syncthreads();

  // Phase B: all 128 j columns, Ahat in regs, ksm via LDS.128 broadcast.
  long ob = (long)bc * Hz * Hz + i;
#pragma unroll 4
  for (int j0 = 0; j0 < Hz; j0 += 4) {
    float a0 = 0.f, a1 = 0.f, a2 = 0.f, a3 = 0.f;
#pragma unroll
    for (int s = 0; s < Sc; s++) {
      float4 kv = *(const float4*)&ksm[s][j0];
      float ar = Areg[s];
      a0 = fmaf(ar, kv.x, a0);
      a1 = fmaf(ar, kv.y, a1);
      a2 = fmaf(ar, kv.z, a2);
      a3 = fmaf(ar, kv.w, a3);
    }
    gS[ob + (long)(j0 + 0) * Hz] = sp * a0;
    gS[ob + (long)(j0 + 1) * Hz] = sp * a1;
    gS[ob + (long)(j0 + 2) * Hz] = sp * a2;
    gS[ob + (long)(j0 + 3) * Hz] = sp * a3;
  }
}

// ---------------------------------------------------------------------------
// Kernel 3: serial chunk-scan of scalar n per channel (32 steps).
// ---------------------------------------------------------------------------
__global__ __launch_bounds__(128) void nchunk_k() {
  int b = blockIdx.x;
  int i = threadIdx.x;
  float n = 0.f;
  for (int c = 0; c < NC; c++) {
    gNst[(b * NC + c) * Hz + i] = n;
    int rb = (b * Tz + c * Sc) * Hz;
    float s = 0.f;
#pragma unroll
    for (int t = 0; t < Sc; t++) s += gAk[rb + t * Hz + i];
    n = fmaf(gPtot[(b * NC + c) * Hz + i], n,
             gsqP[(b * NC + c) * Hz + i] * s);
  }
}

// ---------------------------------------------------------------------------
// Kernel 4: streaming chunk-state scan (serial over c, parallel over b,i,j).
// ---------------------------------------------------------------------------
__global__ __launch_bounds__(128) void combine_k() {
  int b = blockIdx.x >> 7;
  int j = blockIdx.x & 127;
  int i = threadIdx.x;
  long base = ((long)b * NC * Hz + j) * Hz + i;   // c stride = Hz*Hz
  int pbase = b * NC * Hz + i;                    // c stride = Hz

  float C = 0.f;
  for (int c = 0; c < NC; c += 4) {
    float s0 = gS[base + (long)(c + 0) * Hz * Hz];
    float s1 = gS[base + (long)(c + 1) * Hz * Hz];
    float s2 = gS[base + (long)(c + 2) * Hz * Hz];
    float s3 = gS[base + (long)(c + 3) * Hz * Hz];
    float p0 = gPtot[pbase + (c + 0) * Hz];
    float p1 = gPtot[pbase + (c + 1) * Hz];
    float p2 = gPtot[pbase + (c + 2) * Hz];
    float p3 = gPtot[pbase + (c + 3) * Hz];
    gCst[base + (long)(c + 0) * Hz * Hz] = C;
    C = fmaf(p0, C, s0);
    gCst[base + (long)(c + 1) * Hz * Hz] = C;
    C = fmaf(p1, C, s1);
    gCst[base + (long)(c + 2) * Hz * Hz] = C;
    C = fmaf(p2, C, s2);
    gCst[base + (long)(c + 3) * Hz * Hz] = C;
    C = fmaf(p3, C, s3);
  }
}

// ---------------------------------------------------------------------------
// Kernel 5: per-chunk outputs + fused denominator.
// den[t] = max(|n_{t-1}.q_t|,1) computed in-block (same reduction as old nden_k).
// h~[t][i] = Pprev[t][i]*(sum_{s<t} G[t][s]*Ahat[s][i] + sqrtP_i*(Cst[i,:].q_t))
// h = o * h~ / den.  grid = Bz*NC, block = 128 (thread = i).
// ---------------------------------------------------------------------------
__global__ __launch_bounds__(128) void out_k(float* dout, int last) {
  __shared__ float qsm[Sc][132];
  __shared__ float ksm[Sc][132];
  __shared__ float Asm[Sc][128];
  __shared__ float dsm[Sc][128];
  __shared__ float Gs[Sc][Sc];
  __shared__ float den_s[Sc];

  int bc = blockIdx.x;
  int tid = threadIdx.x;
  int row0 = bc * Sc * Hz;
  float* outp = last ? dout : gh1;

  // stage q/k/A; thread tid owns column d = tid for all t -> fuse den partials
  float run = gsqP[bc * Hz + tid] * gNst[bc * Hz + tid];
#pragma unroll
  for (int t = 0; t < Sc; t++) {
    int idx = row0 + t * Hz + tid;
    float qv = gq[idx];
    qsm[t][tid] = qv;
    ksm[t][tid] = gk[idx];
    Asm[t][tid] = gA[idx];
    dsm[t][tid] = gPprev[idx] * run * qv;
    run += gAk[idx];
  }
  __syncthreads();

  // G[t][s] = k_s . q_t (strict lower; zero elsewhere)
#pragma unroll
  for (int e0 = 0; e0 < 2; e0++) {
    int e = tid + e0 * 128;
    int t = e >> 4, s = e & 15;
    float gacc = 0.f;
    if (s < t) {
#pragma unroll 8
      for (int d4 = 0; d4 < 32; d4++) {
        float4 kk = *(const float4*)&ksm[s][4 * d4];
        float4 qq = *(const float4*)&qsm[t][4 * d4];
        gacc = fmaf(kk.x, qq.x, gacc);
        gacc = fmaf(kk.y, qq.y, gacc);
        gacc = fmaf(kk.z, qq.z, gacc);
        gacc = fmaf(kk.w, qq.w, gacc);
      }
    }
    Gs[t][s] = gacc;
  }

  // den reduction (identical order to old nden_k)
  {
    int w = tid >> 5, lane = tid & 31;
#pragma unroll
    for (int tt = 0; tt < 4; tt++) {
      int t = w * 4 + tt;
      float s = dsm[t][lane] + dsm[t][lane + 32] + dsm[t][lane + 64] + dsm[t][lane + 96];
#pragma unroll
      for (int o = 16; o; o >>= 1) s += __shfl_xor_sync(0xffffffffu, s, o);
      if (lane == 0) den_s[t] = fmaxf(fabsf(s), 1.f);
    }
  }
  __syncthreads();

  int i = tid;
  float acc[Sc];
#pragma unroll
  for (int t = 0; t < Sc; t++) acc[t] = 0.f;

  // inter: acc[t] += Cstart[i][j] * q_t[j]; coalesced LDG, 16-j batches
  const float* cbase = gCst + (long)bc * Hz * Hz + i;
  for (int j0 = 0; j0 < Hz; j0 += 16) {
    float cj[16];
#pragma unroll
    for (int jj = 0; jj < 16; jj++) cj[jj] = cbase[(j0 + jj) * Hz];
#pragma unroll
    for (int t = 0; t < Sc; t++) {
#pragma unroll
      for (int jj4 = 0; jj4 < 4; jj4++) {
        float4 qq = *(const float4*)&qsm[t][j0 + 4 * jj4];
        acc[t] = fmaf(cj[4 * jj4 + 0], qq.x, acc[t]);
        acc[t] = fmaf(cj[4 * jj4 + 1], qq.y, acc[t]);
        acc[t] = fmaf(cj[4 * jj4 + 2], qq.z, acc[t]);
        acc[t] = fmaf(cj[4 * jj4 + 3], qq.w, acc[t]);
      }
    }
  }
  float sp = gsqP[bc * Hz + i];
#pragma unroll
  for (int t = 0; t < Sc; t++) acc[t] *= sp;

  // intra: acc[t] += sum_s G[t][s] * Ahat[s][i]
#pragma unroll
  for (int s4 = 0; s4 < 4; s4++) {
    float a0 = Asm[4 * s4 + 0][i];
    float a1 = Asm[4 * s4 + 1][i];
    float a2 = Asm[4 * s4 + 2][i];
    float a3 = Asm[4 * s4 + 3][i];
#pragma unroll
    for (int t = 0; t < Sc; t++) {
      float4 g = *(const float4*)&Gs[t][4 * s4];
      acc[t] = fmaf(g.x, a0, acc[t]);
      acc[t] = fmaf(g.y, a1, acc[t]);
      acc[t] = fmaf(g.z, a2, acc[t]);
      acc[t] = fmaf(g.w, a3, acc[t]);
    }
  }

  // epilogue
#pragma unroll
  for (int t = 0; t < Sc; t++) {
    int idx = row0 + t * Hz + i;
    float ht = gPprev[idx] * acc[t];
    outp[idx] = go[idx] * __fdividef(ht, den_s[t]);
  }
}

// ---------------------------------------------------------------------------
// Host launch. Two-stream fork (nchunk || combine), event-joined; capturable.
// ---------------------------------------------------------------------------
extern "C" void kernel_launch(void* const* d_in, const int* in_sizes, int n_in,
                              void* d_out, int out_size) {
  static cudaStream_t s2 = nullptr;
  static cudaEvent_t evFork = nullptr, evJoin = nullptr;
  if (s2 == nullptr) {
    cudaStreamCreateWithFlags(&s2, cudaStreamNonBlocking);
    cudaEventCreateWithFlags(&evFork, cudaEventDisableTiming);
    cudaEventCreateWithFlags(&evJoin, cudaEventDisableTiming);
  }

  const float* x = (const float*)d_in[0];
  const float* W[6];
  const float* Bb[6];

  if (n_in >= 13 && in_sizes[2] == Lz * Hz) {
    for (int j = 0; j < 6; j++) {
      W[j]  = (const float*)d_in[1 + 2 * j];
      Bb[j] = (const float*)d_in[2 + 2 * j];
    }
  } else {
    for (int j = 0; j < 6; j++) {
      W[j]  = (const float*)d_in[1 + j];
      Bb[j] = (const float*)d_in[7 + j];
    }
  }

  for (int l = 0; l < Lz; l++) {
    GemmArgs a;
    a.X = x;
    a.use_h1 = l;
    for (int j = 0; j < 6; j++) {
      a.W[j]    = W[j]  + l * Hz * Dz;
      a.bias[j] = Bb[j] + l * Hz;
    }
    gemm_act<<<dim3(BT / 128, 6), 256>>>(a);
    cumsum_k<<<Bz * NC, 128>>>();

    // fork: n-scan on s2, C-path on main stream
    cudaEventRecord(evFork, 0);
    cudaStreamWaitEvent(s2, evFork, 0);
    nchunk_k<<<Bz, 128, 0, s2>>>();
    cudaEventRecord(evJoin, s2);

    combine_k<<<Bz * Hz, 128>>>();

    cudaStreamWaitEvent(0, evJoin, 0);
    out_k<<<Bz * NC, 128>>>((float*)d_out, (l == Lz - 1) ? 1 : 0);
  }
}

// round 11
// speedup vs baseline: 10.2383x; 1.1080x over previous
#include <cuda_runtime.h>
#include <math.h>

#define Bz 8
#define Tz 512
#define Dz 128
#define Hz 128
#define BT (Bz*Tz)          // 4096
#define BTH (BT*Hz)         // 524288
#define Lz 2
#define Sc 16               // chunk size
#define NC (Tz/Sc)          // 32 chunks

// ---- scratch (device globals; no allocation allowed) ----
__device__ __align__(128) float gq[BTH];
__device__ __align__(128) float gk[BTH];     // pre-scaled by 1/sqrt(H)
__device__ __align__(128) float gv[BTH];
__device__ __align__(128) float gi[BTH];     // exp(zi)
__device__ __align__(128) float gf[BTH];     // sigmoid(zf)
__device__ __align__(128) float go[BTH];     // sigmoid(zo)
__device__ __align__(128) float gh1[BTH];    // layer-1 output
// chunked-scan scratch
__device__ __align__(128) float gA[BTH];       // Ahat[s][i] = i*v / Pn[s]
__device__ __align__(128) float gAk[BTH];      // ikhat[s][i] = i*k / Pn[s]
__device__ __align__(128) float gPprev[BTH];   // Pn[t-1] (t=0 slot = 1/sqrt(Ptot))
__device__ __align__(128) float gsqP[Bz*NC*Hz];  // sqrt(Ptot)
__device__ __align__(128) float gPtot[Bz*NC*Hz]; // Ptot
__device__ __align__(128) float gnS[Bz*NC*Hz];   // sqrtP * sum_s ikhat[s]
__device__ __align__(128) float gNst[Bz*NC*Hz];  // chunk-start n
__device__ __align__(128) float gS[Bz*NC*Hz*Hz]; // chunk sums -> (in-place) chunk-start C

struct GemmArgs {
  const float* X;
  const float* W[6];
  const float* bias[6];
  int use_h1;
};

// ---- f32x2 packed helpers (sm_103a FFMA2 path; only reachable via PTX) ----
__device__ __forceinline__ unsigned long long dup2(float x) {
  unsigned long long r;
  asm("mov.b64 %0, {%1, %1};" : "=l"(r) : "r"(__float_as_int(x)));
  return r;
}
__device__ __forceinline__ unsigned long long fma2(unsigned long long a,
                                                   unsigned long long b,
                                                   unsigned long long c) {
  unsigned long long d;
  asm("fma.rn.f32x2 %0, %1, %2, %3;" : "=l"(d) : "l"(a), "l"(b), "l"(c));
  return d;
}
__device__ __forceinline__ void unpack2(unsigned long long p, float& lo, float& hi) {
  int a, b;
  asm("mov.b64 {%0, %1}, %2;" : "=r"(a), "=r"(b) : "l"(p));
  lo = __int_as_float(a);
  hi = __int_as_float(b);
}

// ---------------------------------------------------------------------------
// Kernel 1: fused 6-way projection GEMM + activations, FFMA2 inner loop.
// 128(n) x 128(m) tile, 256 threads, 8x8 microtile, grid (32, 6).
// A staged DUPLICATED as float2 pairs [n][k] (ull, stride 34).
// B staged TRANSPOSED [k][m] floats (stride 130); thread's m = 32*jp + 2*tx.
// Accumulators pack the m-pair dimension (4 ull per row i).
// ---------------------------------------------------------------------------
#define SA 34    // As2 row stride in 8B units (even -> 16B-aligned pairs)
#define SB 130   // Bs row stride in floats (even -> 8B-aligned pairs)
__global__ __launch_bounds__(256) void gemm_act(GemmArgs a) {
  __shared__ __align__(16) unsigned long long As2[128 * SA];
  __shared__ __align__(16) float Bs[32 * SB];
  const float* Xp = a.use_h1 ? gh1 : a.X;

  int tid = threadIdx.x;
  int n0 = blockIdx.x * 128;
  int p = blockIdx.y;
  const float* Wp = a.W[p];

  int tx = tid & 15, ty = tid >> 4;
  int sn = tid >> 3, sk4 = tid & 7;   // staging coords (n/m = sn + s*32, k4 = sk4)

  unsigned long long acc[8][4];
#pragma unroll
  for (int i = 0; i < 8; i++)
#pragma unroll
    for (int j = 0; j < 4; j++) acc[i][j] = 0ULL;

  float4 xr[4], wr[4];
#pragma unroll
  for (int s = 0; s < 4; s++) {
    int n = sn + s * 32;
    xr[s] = *(const float4*)(Xp + (n0 + n) * Dz + 4 * sk4);
    wr[s] = *(const float4*)(Wp + n * Dz + 4 * sk4);
  }

  for (int it = 0; it < 4; it++) {
#pragma unroll
    for (int s = 0; s < 4; s++) {
      int n = sn + s * 32;
      unsigned long long* arow = &As2[n * SA + 4 * sk4];
      arow[0] = dup2(xr[s].x);
      arow[1] = dup2(xr[s].y);
      arow[2] = dup2(xr[s].z);
      arow[3] = dup2(xr[s].w);
      // B transpose: Bs[k][m]
      Bs[(4 * sk4 + 0) * SB + n] = wr[s].x;
      Bs[(4 * sk4 + 1) * SB + n] = wr[s].y;
      Bs[(4 * sk4 + 2) * SB + n] = wr[s].z;
      Bs[(4 * sk4 + 3) * SB + n] = wr[s].w;
    }
    __syncthreads();
    if (it < 3) {
      int kk = (it + 1) * 32;
#pragma unroll
      for (int s = 0; s < 4; s++) {
        int n = sn + s * 32;
        xr[s] = *(const float4*)(Xp + (n0 + n) * Dz + kk + 4 * sk4);
        wr[s] = *(const float4*)(Wp + n * Dz + kk + 4 * sk4);
      }
    }
#pragma unroll 4
    for (int k = 0; k < 32; k += 2) {
      unsigned long long a0[8], a1[8];
#pragma unroll
      for (int i = 0; i < 8; i++) {
        ulonglong2 av = *(const ulonglong2*)&As2[(ty * 8 + i) * SA + k];
        a0[i] = av.x;
        a1[i] = av.y;
      }
      unsigned long long bv0[4], bv1[4];
#pragma unroll
      for (int jp = 0; jp < 4; jp++) {
        bv0[jp] = *(const unsigned long long*)&Bs[k * SB + 32 * jp + 2 * tx];
        bv1[jp] = *(const unsigned long long*)&Bs[(k + 1) * SB + 32 * jp + 2 * tx];
      }
#pragma unroll
      for (int i = 0; i < 8; i++)
#pragma unroll
        for (int jp = 0; jp < 4; jp++)
          acc[i][jp] = fma2(a0[i], bv0[jp], acc[i][jp]);
#pragma unroll
      for (int i = 0; i < 8; i++)
#pragma unroll
        for (int jp = 0; jp < 4; jp++)
          acc[i][jp] = fma2(a1[i], bv1[jp], acc[i][jp]);
    }
    __syncthreads();
  }

  float* outs;
  switch (p) {
    case 0: outs = gq; break;
    case 1: outs = gk; break;
    case 2: outs = gv; break;
    case 3: outs = gi; break;
    case 4: outs = gf; break;
    default: outs = go; break;
  }
  const float kscale = 0.08838834764831845f;  // 1/sqrt(128)
  const float* bp = a.bias[p];
#pragma unroll
  for (int i = 0; i < 8; i++) {
    int n = n0 + ty * 8 + i;
#pragma unroll
    for (int jp = 0; jp < 4; jp++) {
      int m = 32 * jp + 2 * tx;
      float lo, hi;
      unpack2(acc[i][jp], lo, hi);
      float2 bb = *(const float2*)&bp[m];
      float v0 = lo + bb.x, v1 = hi + bb.y;
      float r0, r1;
      if (p == 0)      { r0 = v0; r1 = v1; }
      else if (p == 1) { r0 = v0 * kscale; r1 = v1 * kscale; }
      else if (p == 2) { r0 = v0; r1 = v1; }
      else if (p == 3) { r0 = __expf(v0); r1 = __expf(v1); }
      else             { r0 = __fdividef(1.f, 1.f + __expf(-v0));
                         r1 = __fdividef(1.f, 1.f + __expf(-v1)); }
      *(float2*)&outs[n * Hz + m] = make_float2(r0, r1);
    }
  }
}

// ---------------------------------------------------------------------------
// Kernel 2: fused per-chunk cumsum + local state sums (+ n chunk-sums).
// ---------------------------------------------------------------------------
__global__ __launch_bounds__(128) void cumsum_k() {
  __shared__ float ksm[Sc][128];
  int bc = blockIdx.x;
  int i = threadIdx.x;
  int base = bc * Sc * Hz + i;

  float lf[Sc];
  float ct = 0.f;
#pragma unroll
  for (int t = 0; t < Sc; t++) {
    float f = gf[base + t * Hz];
    float l = __logf(f);
    lf[t] = l;
    ct += l;
  }
  float sq2 = 0.5f * ct;

  gPprev[base] = __expf(-sq2);   // t=0 slot: Pn[-1] = 1/sqrt(Ptot)
  float Areg[Sc];
  float c_run = 0.f;
  float sAk = 0.f;
#pragma unroll
  for (int t = 0; t < Sc; t++) {
    c_run += lf[t];
    float e = __expf(sq2 - c_run);
    float ii = gi[base + t * Hz];
    float kk = gk[base + t * Hz];
    float av = ii * gv[base + t * Hz] * e;
    float akv = ii * kk * e;
    Areg[t] = av;
    gA[base + t * Hz]  = av;
    gAk[base + t * Hz] = akv;
    sAk += akv;
    ksm[t][i] = kk;
    if (t < Sc - 1) gPprev[base + (t + 1) * Hz] = __expf(c_run - sq2);
  }
  float sp = __expf(sq2);
  gsqP[bc * Hz + i]  = sp;
  gPtot[bc * Hz + i] = __expf(ct);
  gnS[bc * Hz + i]   = sp * sAk;
  __syncthreads();

  // Phase B: all 128 j columns, Ahat in regs, ksm via LDS.128 broadcast.
  long ob = (long)bc * Hz * Hz + i;
#pragma unroll 4
  for (int j0 = 0; j0 < Hz; j0 += 4) {
    float a0 = 0.f, a1 = 0.f, a2 = 0.f, a3 = 0.f;
#pragma unroll
    for (int s = 0; s < Sc; s++) {
      float4 kv = *(const float4*)&ksm[s][j0];
      float ar = Areg[s];
      a0 = fmaf(ar, kv.x, a0);
      a1 = fmaf(ar, kv.y, a1);
      a2 = fmaf(ar, kv.z, a2);
      a3 = fmaf(ar, kv.w, a3);
    }
    gS[ob + (long)(j0 + 0) * Hz] = sp * a0;
    gS[ob + (long)(j0 + 1) * Hz] = sp * a1;
    gS[ob + (long)(j0 + 2) * Hz] = sp * a2;
    gS[ob + (long)(j0 + 3) * Hz] = sp * a3;
  }
}

// ---------------------------------------------------------------------------
// Kernel 3: streaming chunk-state scan, IN-PLACE (gS -> chunk-start C),
// with the scalar n-scan folded in as the last Bz blocks.
// grid = Bz*Hz + Bz, block = 128.
// ---------------------------------------------------------------------------
__global__ __launch_bounds__(128) void combine_k() {
  int blk = blockIdx.x;
  int i = threadIdx.x;
  if (blk < Bz * Hz) {
    int b = blk >> 7;
    int j = blk & 127;
    long base = ((long)b * NC * Hz + j) * Hz + i;   // c stride = Hz*Hz
    int pbase = b * NC * Hz + i;                    // c stride = Hz
    const long CS = (long)Hz * Hz;

    float C = 0.f;
    float s_next = gS[base];
#pragma unroll 4
    for (int c = 0; c < NC; c++) {
      float s = s_next;
      if (c + 1 < NC) s_next = gS[base + (long)(c + 1) * CS];
      float pt = gPtot[pbase + c * Hz];
      gS[base + (long)c * CS] = C;   // overwrite with chunk-start state
      C = fmaf(pt, C, s);
    }
  } else {
    int b = blk - Bz * Hz;
    float n = 0.f;
#pragma unroll 4
    for (int c = 0; c < NC; c++) {
      int o = (b * NC + c) * Hz + i;
      gNst[o] = n;
      n = fmaf(gPtot[o], n, gnS[o]);
    }
  }
}

// ---------------------------------------------------------------------------
// Kernel 4: per-chunk outputs + fused denominator. Cstart read from gS.
// ---------------------------------------------------------------------------
__global__ __launch_bounds__(128) void out_k(float* dout, int last) {
  __shared__ float qsm[Sc][132];
  __shared__ float ksm[Sc][132];
  __shared__ float Asm[Sc][128];
  __shared__ float dsm[Sc][128];
  __shared__ float Gs[Sc][Sc];
  __shared__ float den_s[Sc];

  int bc = blockIdx.x;
  int tid = threadIdx.x;
  int row0 = bc * Sc * Hz;
  float* outp = last ? dout : gh1;

  float run = gsqP[bc * Hz + tid] * gNst[bc * Hz + tid];
#pragma unroll
  for (int t = 0; t < Sc; t++) {
    int idx = row0 + t * Hz + tid;
    float qv = gq[idx];
    qsm[t][tid] = qv;
    ksm[t][tid] = gk[idx];
    Asm[t][tid] = gA[idx];
    dsm[t][tid] = gPprev[idx] * run * qv;
    run += gAk[idx];
  }
  __syncthreads();

  // G[t][s] = k_s . q_t (strict lower; zero elsewhere)
#pragma unroll
  for (int e0 = 0; e0 < 2; e0++) {
    int e = tid + e0 * 128;
    int t = e >> 4, s = e & 15;
    float gacc = 0.f;
    if (s < t) {
#pragma unroll 8
      for (int d4 = 0; d4 < 32; d4++) {
        float4 kk = *(const float4*)&ksm[s][4 * d4];
        float4 qq = *(const float4*)&qsm[t][4 * d4];
        gacc = fmaf(kk.x, qq.x, gacc);
        gacc = fmaf(kk.y, qq.y, gacc);
        gacc = fmaf(kk.z, qq.z, gacc);
        gacc = fmaf(kk.w, qq.w, gacc);
      }
    }
    Gs[t][s] = gacc;
  }

  // den reduction
  {
    int w = tid >> 5, lane = tid & 31;
#pragma unroll
    for (int tt = 0; tt < 4; tt++) {
      int t = w * 4 + tt;
      float s = dsm[t][lane] + dsm[t][lane + 32] + dsm[t][lane + 64] + dsm[t][lane + 96];
#pragma unroll
      for (int o = 16; o; o >>= 1) s += __shfl_xor_sync(0xffffffffu, s, o);
      if (lane == 0) den_s[t] = fmaxf(fabsf(s), 1.f);
    }
  }
  __syncthreads();

  int i = tid;
  float acc[Sc];
#pragma unroll
  for (int t = 0; t < Sc; t++) acc[t] = 0.f;

  // inter: acc[t] += Cstart[i][j] * q_t[j]; coalesced LDG from gS, 16-j batches
  const float* cbase = gS + (long)bc * Hz * Hz + i;
  for (int j0 = 0; j0 < Hz; j0 += 16) {
    float cj[16];
#pragma unroll
    for (int jj = 0; jj < 16; jj++) cj[jj] = cbase[(j0 + jj) * Hz];
#pragma unroll
    for (int t = 0; t < Sc; t++) {
#pragma unroll
      for (int jj4 = 0; jj4 < 4; jj4++) {
        float4 qq = *(const float4*)&qsm[t][j0 + 4 * jj4];
        acc[t] = fmaf(cj[4 * jj4 + 0], qq.x, acc[t]);
        acc[t] = fmaf(cj[4 * jj4 + 1], qq.y, acc[t]);
        acc[t] = fmaf(cj[4 * jj4 + 2], qq.z, acc[t]);
        acc[t] = fmaf(cj[4 * jj4 + 3], qq.w, acc[t]);
      }
    }
  }
  float sp = gsqP[bc * Hz + i];
#pragma unroll
  for (int t = 0; t < Sc; t++) acc[t] *= sp;

  // intra: acc[t] += sum_s G[t][s] * Ahat[s][i]
#pragma unroll
  for (int s4 = 0; s4 < 4; s4++) {
    float a0 = Asm[4 * s4 + 0][i];
    float a1 = Asm[4 * s4 + 1][i];
    float a2 = Asm[4 * s4 + 2][i];
    float a3 = Asm[4 * s4 + 3][i];
#pragma unroll
    for (int t = 0; t < Sc; t++) {
      float4 g = *(const float4*)&Gs[t][4 * s4];
      acc[t] = fmaf(g.x, a0, acc[t]);
      acc[t] = fmaf(g.y, a1, acc[t]);
      acc[t] = fmaf(g.z, a2, acc[t]);
      acc[t] = fmaf(g.w, a3, acc[t]);
    }
  }

  // epilogue
#pragma unroll
  for (int t = 0; t < Sc; t++) {
    int idx = row0 + t * Hz + i;
    float ht = gPprev[idx] * acc[t];
    outp[idx] = go[idx] * __fdividef(ht, den_s[t]);
  }
}

// ---------------------------------------------------------------------------
// Host launch: 4 kernels per layer, single stream.
// ---------------------------------------------------------------------------
extern "C" void kernel_launch(void* const* d_in, const int* in_sizes, int n_in,
                              void* d_out, int out_size) {
  const float* x = (const float*)d_in[0];
  const float* W[6];
  const float* Bb[6];

  if (n_in >= 13 && in_sizes[2] == Lz * Hz) {
    for (int j = 0; j < 6; j++) {
      W[j]  = (const float*)d_in[1 + 2 * j];
      Bb[j] = (const float*)d_in[2 + 2 * j];
    }
  } else {
    for (int j = 0; j < 6; j++) {
      W[j]  = (const float*)d_in[1 + j];
      Bb[j] = (const float*)d_in[7 + j];
    }
  }

  for (int l = 0; l < Lz; l++) {
    GemmArgs a;
    a.X = x;
    a.use_h1 = l;
    for (int j = 0; j < 6; j++) {
      a.W[j]    = W[j]  + l * Hz * Dz;
      a.bias[j] = Bb[j] + l * Hz;
    }
    gemm_act<<<dim3(BT / 128, 6), 256>>>(a);
    cumsum_k<<<Bz * NC, 128>>>();
    combine_k<<<Bz * Hz + Bz, 128>>>();
    out_k<<<Bz * NC, 128>>>((float*)d_out, (l == Lz - 1) ? 1 : 0);
  }
}